// round 1
// baseline (speedup 1.0000x reference)
#include <cuda_runtime.h>

#define DIM    1024
#define HEADS  16
#define HD     64
#define BATCH  4
#define SEQ    2048
#define MROWS  (BATCH * SEQ)            // 8192
#define SEQHD  (SEQ * HD)               // 131072
#define QKV_ELEMS (BATCH * HEADS * SEQ * HD)  // 8388608

// Scratch (allocation-free rule: __device__ globals)
__device__ float g_Q[QKV_ELEMS];
__device__ float g_K[QKV_ELEMS];
__device__ float g_V[QKV_ELEMS];
__device__ float g_O[QKV_ELEMS];

// ---------------------------------------------------------------------------
// Kernel 1: fused QKV projection.
// Y = x @ W (W in {Wq,Wk,Wv} selected per column-tile), output scattered into
// [b, h, n, d] layout. 128x128 tile, BK=8, 256 threads, 8x8 micro-tile split
// as 2x2 groups of 4x4 (cols tx*4 and tx*4+64 -> conflict-free LDS.128).
// ---------------------------------------------------------------------------
__global__ __launch_bounds__(256) void qkv_gemm(const float* __restrict__ x,
                                                const float* __restrict__ Wq,
                                                const float* __restrict__ Wk,
                                                const float* __restrict__ Wv) {
    __shared__ float As[8][132];   // transposed A tile, padded
    __shared__ float Bs[8][128];

    const int bx = blockIdx.x;                 // 0..23  (3072 cols / 128)
    const int by = blockIdx.y;                 // 0..63  (8192 rows / 128)
    const int wsel = (bx * 128) >> 10;         // which weight
    const float* __restrict__ W = (wsel == 0) ? Wq : ((wsel == 1) ? Wk : Wv);
    const int col0 = (bx * 128) & 1023;
    const int row0 = by * 128;

    const int tid = threadIdx.x;
    const int ty = tid >> 4, tx = tid & 15;

    const int arow = tid >> 1;                 // 0..127
    const int acol = (tid & 1) << 2;           // 0 or 4
    const int brow = tid >> 5;                 // 0..7
    const int bcol = (tid & 31) << 2;          // 0..124

    const float* Ag = x + (row0 + arow) * DIM + acol;
    const float* Bg = W + brow * DIM + col0 + bcol;

    float acc[8][8];
#pragma unroll
    for (int i = 0; i < 8; i++)
#pragma unroll
        for (int j = 0; j < 8; j++) acc[i][j] = 0.0f;

    float4 aR = *(const float4*)Ag;
    float4 bR = *(const float4*)Bg;

    for (int k0 = 0; k0 < DIM; k0 += 8) {
        As[acol + 0][arow] = aR.x;
        As[acol + 1][arow] = aR.y;
        As[acol + 2][arow] = aR.z;
        As[acol + 3][arow] = aR.w;
        *(float4*)&Bs[brow][bcol] = bR;
        __syncthreads();

        if (k0 + 8 < DIM) {
            aR = *(const float4*)(Ag + k0 + 8);
            bR = *(const float4*)(Bg + (k0 + 8) * DIM);
        }

#pragma unroll
        for (int kk = 0; kk < 8; kk++) {
            float a[8], b[8];
            float4 t;
            t = *(const float4*)&As[kk][ty * 4];       a[0]=t.x; a[1]=t.y; a[2]=t.z; a[3]=t.w;
            t = *(const float4*)&As[kk][ty * 4 + 64];  a[4]=t.x; a[5]=t.y; a[6]=t.z; a[7]=t.w;
            t = *(const float4*)&Bs[kk][tx * 4];       b[0]=t.x; b[1]=t.y; b[2]=t.z; b[3]=t.w;
            t = *(const float4*)&Bs[kk][tx * 4 + 64];  b[4]=t.x; b[5]=t.y; b[6]=t.z; b[7]=t.w;
#pragma unroll
            for (int i = 0; i < 8; i++)
#pragma unroll
                for (int j = 0; j < 8; j++)
                    acc[i][j] += a[i] * b[j];
        }
        __syncthreads();
    }

    float* __restrict__ dst = (wsel == 0) ? g_Q : ((wsel == 1) ? g_K : g_V);
#pragma unroll
    for (int ih = 0; ih < 2; ih++) {
#pragma unroll
        for (int ii = 0; ii < 4; ii++) {
            const int i = ih * 4 + ii;
            const int m = row0 + ih * 64 + ty * 4 + ii;
            const int b_ = m >> 11, n = m & 2047;
#pragma unroll
            for (int jh = 0; jh < 2; jh++) {
                const int cc0 = col0 + jh * 64 + tx * 4;
                const int h = cc0 >> 6, d0 = cc0 & 63;
                float* p = dst + ((b_ * HEADS + h) * SEQ + n) * HD + d0;
                *(float4*)p = make_float4(acc[i][jh * 4 + 0], acc[i][jh * 4 + 1],
                                          acc[i][jh * 4 + 2], acc[i][jh * 4 + 3]);
            }
        }
    }
}

// ---------------------------------------------------------------------------
// Kernel 2: flash attention. One block = one (b,h) x 128 query rows.
// BR=128, BC=64, 256 threads; thread (ty,tx) owns rows ty+16i (i<8), cols
// tx+16j (j<4). V stored transposed in smem so both GEMMs vectorize along k.
// ---------------------------------------------------------------------------
#define BR 128
#define BC 64
#define AST 68   // smem row stride (floats): mult of 4, odd/32 bank spread

__global__ __launch_bounds__(256) void attn_kernel() {
    extern __shared__ float sm[];
    float* sQ  = sm;                    // [128][68]
    float* sK  = sQ  + BR * AST;        // [64][68]
    float* sVt = sK  + BC * AST;        // [64][68]  (transposed: [d][kv])
    float* sP  = sVt + HD * AST;        // [128][68]

    const int bh   = blockIdx.y;        // 0..63
    const int rblk = blockIdx.x;        // 0..15
    const int tid  = threadIdx.x;
    const int ty = tid >> 4, tx = tid & 15;

    const float* Qg = g_Q + (bh * SEQ + rblk * BR) * HD;
    const float* Kg = g_K + bh * SEQ * HD;
    const float* Vg = g_V + bh * SEQ * HD;

    // Load Q tile (128x64)
#pragma unroll
    for (int it = 0; it < 8; it++) {
        int e = tid * 4 + it * 1024;
        int r = e >> 6, d = e & 63;
        *(float4*)&sQ[r * AST + d] = *(const float4*)(Qg + r * HD + d);
    }

    float mi[8], li[8], acc[8][4];
#pragma unroll
    for (int i = 0; i < 8; i++) {
        mi[i] = -1e30f;
        li[i] = 0.0f;
#pragma unroll
        for (int j = 0; j < 4; j++) acc[i][j] = 0.0f;
    }

    for (int c0 = 0; c0 < SEQ; c0 += BC) {
        __syncthreads();   // previous iteration's smem reads done
        // K chunk (64x64)
#pragma unroll
        for (int it = 0; it < 4; it++) {
            int e = tid * 4 + it * 1024;
            int r = e >> 6, d = e & 63;
            *(float4*)&sK[r * AST + d] = *(const float4*)(Kg + (c0 + r) * HD + d);
        }
        // V chunk, transposed into sVt[d][kv]
        {
            const int d  = tid & 63;
            const int kb = tid >> 6;   // 0..3
#pragma unroll
            for (int it = 0; it < 16; it++) {
                int kv = it * 4 + kb;
                sVt[d * AST + kv] = Vg[(c0 + kv) * HD + d];
            }
        }
        __syncthreads();

        // S = Q @ K^T  (128x64 tile, this thread: 8x4)
        float s[8][4];
#pragma unroll
        for (int i = 0; i < 8; i++)
#pragma unroll
            for (int j = 0; j < 4; j++) s[i][j] = 0.0f;

        for (int k = 0; k < HD; k += 4) {
            float4 a[8], b[4];
#pragma unroll
            for (int i = 0; i < 8; i++) a[i] = *(const float4*)&sQ[(ty + 16 * i) * AST + k];
#pragma unroll
            for (int j = 0; j < 4; j++) b[j] = *(const float4*)&sK[(tx + 16 * j) * AST + k];
#pragma unroll
            for (int i = 0; i < 8; i++)
#pragma unroll
                for (int j = 0; j < 4; j++)
                    s[i][j] += a[i].x * b[j].x + a[i].y * b[j].y +
                               a[i].z * b[j].z + a[i].w * b[j].w;
        }

        // online softmax (rows split across 16 lanes of same half-warp)
#pragma unroll
        for (int i = 0; i < 8; i++) {
            float rmax = -1e30f;
#pragma unroll
            for (int j = 0; j < 4; j++) {
                s[i][j] *= 0.125f;               // 1/sqrt(64)
                rmax = fmaxf(rmax, s[i][j]);
            }
#pragma unroll
            for (int off = 8; off > 0; off >>= 1)
                rmax = fmaxf(rmax, __shfl_xor_sync(0xffffffffu, rmax, off, 16));
            float mn = fmaxf(mi[i], rmax);
            float rsum = 0.0f;
#pragma unroll
            for (int j = 0; j < 4; j++) {
                s[i][j] = __expf(s[i][j] - mn);
                rsum += s[i][j];
            }
#pragma unroll
            for (int off = 8; off > 0; off >>= 1)
                rsum += __shfl_xor_sync(0xffffffffu, rsum, off, 16);
            float alpha = __expf(mi[i] - mn);
            li[i] = li[i] * alpha + rsum;
            mi[i] = mn;
#pragma unroll
            for (int j = 0; j < 4; j++) acc[i][j] *= alpha;
        }

        // publish P
#pragma unroll
        for (int i = 0; i < 8; i++)
#pragma unroll
            for (int j = 0; j < 4; j++)
                sP[(ty + 16 * i) * AST + tx + 16 * j] = s[i][j];
        __syncthreads();

        // O += P @ V   (k over BC, Vt gives float4 along k)
        for (int k = 0; k < BC; k += 4) {
            float4 a[8], b[4];
#pragma unroll
            for (int i = 0; i < 8; i++) a[i] = *(const float4*)&sP[(ty + 16 * i) * AST + k];
#pragma unroll
            for (int j = 0; j < 4; j++) b[j] = *(const float4*)&sVt[(tx + 16 * j) * AST + k];
#pragma unroll
            for (int i = 0; i < 8; i++)
#pragma unroll
                for (int j = 0; j < 4; j++)
                    acc[i][j] += a[i].x * b[j].x + a[i].y * b[j].y +
                                 a[i].z * b[j].z + a[i].w * b[j].w;
        }
    }

    float* Og = g_O + (bh * SEQ + rblk * BR) * HD;
#pragma unroll
    for (int i = 0; i < 8; i++) {
        const float inv = 1.0f / li[i];
        const int r = ty + 16 * i;
#pragma unroll
        for (int j = 0; j < 4; j++)
            Og[r * HD + tx + 16 * j] = acc[i][j] * inv;
    }
}

// ---------------------------------------------------------------------------
// Kernel 3: output projection. A = O permuted [b,n,(h,d)] gather, + bias.
// ---------------------------------------------------------------------------
__global__ __launch_bounds__(256) void proj_gemm(const float* __restrict__ Wo,
                                                 const float* __restrict__ bo,
                                                 float* __restrict__ out) {
    __shared__ float As[8][132];
    __shared__ float Bs[8][128];

    const int bx = blockIdx.x;                 // 0..7
    const int by = blockIdx.y;                 // 0..63
    const int col0 = bx * 128;
    const int row0 = by * 128;

    const int tid = threadIdx.x;
    const int ty = tid >> 4, tx = tid & 15;

    const int arow = tid >> 1;
    const int acol = (tid & 1) << 2;
    const int brow = tid >> 5;
    const int bcol = (tid & 31) << 2;

    const int am = row0 + arow;
    const int ab = am >> 11, an = am & 2047;
    const int abase = ab * (HEADS * SEQHD) + an * HD;   // + (k>>6)*SEQHD + (k&63)

    const float* Bg = Wo + brow * DIM + col0 + bcol;

    float acc[8][8];
#pragma unroll
    for (int i = 0; i < 8; i++)
#pragma unroll
        for (int j = 0; j < 8; j++) acc[i][j] = 0.0f;

    float4 aR = *(const float4*)(g_O + abase + ((acol) >> 6) * SEQHD + (acol & 63));
    float4 bR = *(const float4*)Bg;

    for (int k0 = 0; k0 < DIM; k0 += 8) {
        As[acol + 0][arow] = aR.x;
        As[acol + 1][arow] = aR.y;
        As[acol + 2][arow] = aR.z;
        As[acol + 3][arow] = aR.w;
        *(float4*)&Bs[brow][bcol] = bR;
        __syncthreads();

        if (k0 + 8 < DIM) {
            const int k = k0 + 8 + acol;
            aR = *(const float4*)(g_O + abase + (k >> 6) * SEQHD + (k & 63));
            bR = *(const float4*)(Bg + (k0 + 8) * DIM);
        }

#pragma unroll
        for (int kk = 0; kk < 8; kk++) {
            float a[8], b[8];
            float4 t;
            t = *(const float4*)&As[kk][ty * 4];       a[0]=t.x; a[1]=t.y; a[2]=t.z; a[3]=t.w;
            t = *(const float4*)&As[kk][ty * 4 + 64];  a[4]=t.x; a[5]=t.y; a[6]=t.z; a[7]=t.w;
            t = *(const float4*)&Bs[kk][tx * 4];       b[0]=t.x; b[1]=t.y; b[2]=t.z; b[3]=t.w;
            t = *(const float4*)&Bs[kk][tx * 4 + 64];  b[4]=t.x; b[5]=t.y; b[6]=t.z; b[7]=t.w;
#pragma unroll
            for (int i = 0; i < 8; i++)
#pragma unroll
                for (int j = 0; j < 8; j++)
                    acc[i][j] += a[i] * b[j];
        }
        __syncthreads();
    }

    const float4 bias0 = *(const float4*)&bo[col0 + tx * 4];
    const float4 bias1 = *(const float4*)&bo[col0 + 64 + tx * 4];
#pragma unroll
    for (int ih = 0; ih < 2; ih++) {
#pragma unroll
        for (int ii = 0; ii < 4; ii++) {
            const int i = ih * 4 + ii;
            const int m = row0 + ih * 64 + ty * 4 + ii;
            float* p0 = out + m * DIM + col0 + tx * 4;
            *(float4*)p0 = make_float4(acc[i][0] + bias0.x, acc[i][1] + bias0.y,
                                       acc[i][2] + bias0.z, acc[i][3] + bias0.w);
            float* p1 = out + m * DIM + col0 + 64 + tx * 4;
            *(float4*)p1 = make_float4(acc[i][4] + bias1.x, acc[i][5] + bias1.y,
                                       acc[i][6] + bias1.z, acc[i][7] + bias1.w);
        }
    }
}

// ---------------------------------------------------------------------------

extern "C" void kernel_launch(void* const* d_in, const int* in_sizes, int n_in,
                              void* d_out, int out_size) {
    (void)in_sizes; (void)n_in; (void)out_size;
    const float* x  = (const float*)d_in[0];
    const float* Wq = (const float*)d_in[1];
    const float* Wk = (const float*)d_in[2];
    const float* Wv = (const float*)d_in[3];
    const float* Wo = (const float*)d_in[4];
    const float* bo = (const float*)d_in[5];
    float* out = (float*)d_out;

    const int attn_smem = (BR + BC + HD + BR) * AST * (int)sizeof(float); // 104448
    cudaFuncSetAttribute(attn_kernel, cudaFuncAttributeMaxDynamicSharedMemorySize,
                         attn_smem);

    qkv_gemm<<<dim3(24, 64), 256>>>(x, Wq, Wk, Wv);
    attn_kernel<<<dim3(16, 64), 256, attn_smem>>>();
    proj_gemm<<<dim3(8, 64), 256>>>(Wo, bo, out);
}

// round 3
// speedup vs baseline: 1.2899x; 1.2899x over previous
#include <cuda_runtime.h>
#include <cuda_bf16.h>
#include <cstdint>

#define DIM    1024
#define HEADS  16
#define HD     64
#define BATCH  4
#define SEQ    2048
#define MROWS  (BATCH * SEQ)            // 8192
#define SEQHD  (SEQ * HD)               // 131072
#define QKV_ELEMS (BATCH * HEADS * SEQ * HD)  // 8388608

// ---------------------------------------------------------------------------
// Scratch (allocation-free rule: __device__ globals)
// ---------------------------------------------------------------------------
__device__ float g_Q[QKV_ELEMS];
__device__ float g_K[QKV_ELEMS];
__device__ float g_V[QKV_ELEMS];
__device__ float g_O[QKV_ELEMS];

// bf16 split operands
__device__ __nv_bfloat16 g_xh[MROWS * DIM];
__device__ __nv_bfloat16 g_xl[MROWS * DIM];
__device__ __nv_bfloat16 g_wh[3 * DIM * DIM];   // W^T rows: [n][k]
__device__ __nv_bfloat16 g_wl[3 * DIM * DIM];
__device__ __nv_bfloat16 g_woh[DIM * DIM];      // Wo^T [n][k]
__device__ __nv_bfloat16 g_wol[DIM * DIM];
__device__ __nv_bfloat16 g_oh[MROWS * DIM];     // attn out [m][h*64+d]
__device__ __nv_bfloat16 g_ol[MROWS * DIM];

// ---------------------------------------------------------------------------
// mma.sync helpers (plain sm_100-safe PTX: ldmatrix sm_75+, bf16 mma sm_80+)
// ---------------------------------------------------------------------------
__device__ __forceinline__ uint32_t smem_u32(const void* p) {
    uint32_t a;
    asm("{ .reg .u64 t; cvta.to.shared.u64 t, %1; cvt.u32.u64 %0, t; }" : "=r"(a) : "l"(p));
    return a;
}
__device__ __forceinline__ void ldsm4(uint32_t& r0, uint32_t& r1, uint32_t& r2, uint32_t& r3,
                                      uint32_t addr) {
    asm volatile("ldmatrix.sync.aligned.m8n8.x4.shared.b16 {%0,%1,%2,%3}, [%4];"
                 : "=r"(r0), "=r"(r1), "=r"(r2), "=r"(r3) : "r"(addr));
}
__device__ __forceinline__ void mma16816(float* d, const uint32_t* a, const uint32_t* b) {
    asm volatile(
        "mma.sync.aligned.m16n8k16.row.col.f32.bf16.bf16.f32 "
        "{%0,%1,%2,%3}, {%4,%5,%6,%7}, {%8,%9}, {%0,%1,%2,%3};"
        : "+f"(d[0]), "+f"(d[1]), "+f"(d[2]), "+f"(d[3])
        : "r"(a[0]), "r"(a[1]), "r"(a[2]), "r"(a[3]), "r"(b[0]), "r"(b[1]));
}

// ---------------------------------------------------------------------------
// Prep: fp32 -> bf16 hi/lo splits (+ weight transposes)
// ---------------------------------------------------------------------------
__device__ __forceinline__ void split2(float v, __nv_bfloat16& h, __nv_bfloat16& l) {
    h = __float2bfloat16(v);
    l = __float2bfloat16(v - __bfloat162float(h));
}

__global__ __launch_bounds__(256) void split_x_kernel(const float* __restrict__ x) {
    int i = (blockIdx.x * 256 + threadIdx.x) * 4;
    float4 v = *(const float4*)(x + i);
    __nv_bfloat16 h0, h1, h2, h3, l0, l1, l2, l3;
    split2(v.x, h0, l0); split2(v.y, h1, l1); split2(v.z, h2, l2); split2(v.w, h3, l3);
    __nv_bfloat162 a = {h0, h1}, b = {h2, h3}, c = {l0, l1}, d = {l2, l3};
    *(__nv_bfloat162*)(g_xh + i)     = a;
    *(__nv_bfloat162*)(g_xh + i + 2) = b;
    *(__nv_bfloat162*)(g_xl + i)     = c;
    *(__nv_bfloat162*)(g_xl + i + 2) = d;
}

__global__ __launch_bounds__(256) void transpose_split_kernel(const float* __restrict__ src,
                                                              __nv_bfloat16* __restrict__ dh,
                                                              __nv_bfloat16* __restrict__ dl) {
    __shared__ float t[32][33];
    const int bx = blockIdx.x * 32;   // n base
    const int by = blockIdx.y * 32;   // k base
    const int x = threadIdx.x, y0 = threadIdx.y;  // block (32,8)
#pragma unroll
    for (int i = 0; i < 32; i += 8)
        t[y0 + i][x] = src[(by + y0 + i) * DIM + bx + x];
    __syncthreads();
#pragma unroll
    for (int i = 0; i < 32; i += 8) {
        float v = t[x][y0 + i];
        __nv_bfloat16 h, l; split2(v, h, l);
        int o = (bx + y0 + i) * DIM + by + x;
        dh[o] = h; dl[o] = l;
    }
}

// g_O [b,h,n,d] fp32 -> g_oh/g_ol [m][h*64+d]
__global__ __launch_bounds__(256) void split_O_kernel() {
    int idx = (blockIdx.x * 256 + threadIdx.x) * 4;
    float4 v = *(const float4*)(g_O + idx);
    int d = idx & 63;
    int n = (idx >> 6) & 2047;
    int h = (idx >> 17) & 15;
    int b = idx >> 21;
    int o = (b * SEQ + n) * DIM + h * HD + d;
    __nv_bfloat16 h0, h1, h2, h3, l0, l1, l2, l3;
    split2(v.x, h0, l0); split2(v.y, h1, l1); split2(v.z, h2, l2); split2(v.w, h3, l3);
    __nv_bfloat162 a = {h0, h1}, bb = {h2, h3}, c = {l0, l1}, e = {l2, l3};
    *(__nv_bfloat162*)(g_oh + o)     = a;
    *(__nv_bfloat162*)(g_oh + o + 2) = bb;
    *(__nv_bfloat162*)(g_ol + o)     = c;
    *(__nv_bfloat162*)(g_ol + o + 2) = e;
}

// ---------------------------------------------------------------------------
// bf16x3 split GEMM on mma.sync. C[m][n] = A[m][:] . B[n][:]
// 128x128 block, BK=64, 8 warps (2x4), warp tile 64x32.
// MODE 0: QKV scatter -> g_Q/g_K/g_V  |  MODE 1: out proj + bias -> d_out
// ---------------------------------------------------------------------------
#define GBK   64
#define GSTR  72    // smem row stride in bf16 (144 B): ldmatrix conflict-free
#define GARR  (128 * GSTR)                   // elems per array
#define GSM_BYTES (4 * GARR * 2)             // 73728

template <int MODE>
__global__ __launch_bounds__(256) void gemm_mma(
    const __nv_bfloat16* __restrict__ Ah, const __nv_bfloat16* __restrict__ Al,
    const __nv_bfloat16* __restrict__ Bh, const __nv_bfloat16* __restrict__ Bl,
    float* __restrict__ outp, const float* __restrict__ bo) {
    extern __shared__ __nv_bfloat16 sm[];
    __nv_bfloat16* SAh = sm;
    __nv_bfloat16* SAl = sm + GARR;
    __nv_bfloat16* SBh = sm + 2 * GARR;
    __nv_bfloat16* SBl = sm + 3 * GARR;

    const int tid  = threadIdx.x;
    const int lane = tid & 31;
    const int wid  = tid >> 5;
    const int wm   = wid & 1;           // 0..1 : 64-row slice
    const int wn   = wid >> 1;          // 0..3 : 32-col slice
    const int row0 = blockIdx.y * 128;
    const int col0 = blockIdx.x * 128;

    const __nv_bfloat16* pAh = Ah + (size_t)row0 * DIM;
    const __nv_bfloat16* pAl = Al + (size_t)row0 * DIM;
    const __nv_bfloat16* pBh = Bh + (size_t)col0 * DIM;
    const __nv_bfloat16* pBl = Bl + (size_t)col0 * DIM;

    const uint32_t sAh = smem_u32(SAh), sAl = smem_u32(SAl);
    const uint32_t sBh = smem_u32(SBh), sBl = smem_u32(SBl);

    float acc[4][4][4];
#pragma unroll
    for (int i = 0; i < 4; i++)
#pragma unroll
        for (int j = 0; j < 4; j++)
#pragma unroll
            for (int q = 0; q < 4; q++) acc[i][j][q] = 0.0f;

    // ldmatrix source addresses (bytes)
    const int a_row = (lane & 15);
    const int a_kof = (lane >> 4) << 3;
    const int b_rof = ((lane >> 4) << 3) + (lane & 7);
    const int b_kof = ((lane >> 3) & 1) << 3;

    for (int c = 0; c < DIM / GBK; ++c) {
        if (c) __syncthreads();
        const int k0 = c * GBK;
#pragma unroll
        for (int it = 0; it < 4; ++it) {
            const int lin = it * 256 + tid;      // 0..1023
            const int r  = lin >> 3;
            const int cg = (lin & 7) * 8;
            const int so = r * GSTR + cg;
            const size_t go = (size_t)r * DIM + k0 + cg;
            *(uint4*)(SAh + so) = *(const uint4*)(pAh + go);
            *(uint4*)(SAl + so) = *(const uint4*)(pAl + go);
            *(uint4*)(SBh + so) = *(const uint4*)(pBh + go);
            *(uint4*)(SBl + so) = *(const uint4*)(pBl + go);
        }
        __syncthreads();

#pragma unroll
        for (int ks = 0; ks < GBK / 16; ++ks) {
            uint32_t ah[4][4], al[4][4], bh[2][4], bl[2][4];
#pragma unroll
            for (int mi = 0; mi < 4; ++mi) {
                const uint32_t off =
                    (uint32_t)(((wm * 64 + mi * 16 + a_row) * GSTR + ks * 16 + a_kof) * 2);
                ldsm4(ah[mi][0], ah[mi][1], ah[mi][2], ah[mi][3], sAh + off);
                ldsm4(al[mi][0], al[mi][1], al[mi][2], al[mi][3], sAl + off);
            }
#pragma unroll
            for (int p = 0; p < 2; ++p) {
                const uint32_t off =
                    (uint32_t)(((wn * 32 + p * 16 + b_rof) * GSTR + ks * 16 + b_kof) * 2);
                ldsm4(bh[p][0], bh[p][1], bh[p][2], bh[p][3], sBh + off);
                ldsm4(bl[p][0], bl[p][1], bl[p][2], bl[p][3], sBl + off);
            }
#pragma unroll
            for (int mi = 0; mi < 4; ++mi)
#pragma unroll
                for (int p = 0; p < 2; ++p)
#pragma unroll
                    for (int q = 0; q < 2; ++q) {
                        float* d = acc[mi][p * 2 + q];
                        mma16816(d, ah[mi], &bh[p][q * 2]);   // hi*hi
                        mma16816(d, ah[mi], &bl[p][q * 2]);   // hi*lo
                        mma16816(d, al[mi], &bh[p][q * 2]);   // lo*hi
                    }
        }
    }

    // Epilogue. acc[mi][nj]: rows wm*64+mi*16 + (lane>>2) (+8), cols wn*32+nj*8+(lane&3)*2
#pragma unroll
    for (int mi = 0; mi < 4; ++mi) {
#pragma unroll
        for (int nj = 0; nj < 4; ++nj) {
            const int r = row0 + wm * 64 + mi * 16 + (lane >> 2);
            const int cgl = col0 + wn * 32 + nj * 8 + (lane & 3) * 2;
#pragma unroll
            for (int half = 0; half < 2; ++half) {
                const int rr = r + half * 8;
                const float v0 = acc[mi][nj][half * 2 + 0];
                const float v1 = acc[mi][nj][half * 2 + 1];
                if (MODE == 0) {
                    const int b_ = rr >> 11, n = rr & 2047;
                    const int wsel = cgl >> 10;
                    const int c1 = cgl & 1023;
                    const int h = c1 >> 6, d0 = c1 & 63;
                    float* dst = (wsel == 0) ? g_Q : ((wsel == 1) ? g_K : g_V);
                    *(float2*)(dst + ((size_t)(b_ * HEADS + h) * SEQ + n) * HD + d0) =
                        make_float2(v0, v1);
                } else {
                    *(float2*)(outp + (size_t)rr * DIM + cgl) =
                        make_float2(v0 + bo[cgl], v1 + bo[cgl + 1]);
                }
            }
        }
    }
}

// ---------------------------------------------------------------------------
// Flash attention (fp32 SIMT) — unchanged from R1 passing version.
// ---------------------------------------------------------------------------
#define BR 128
#define BC 64
#define AST 68

__global__ __launch_bounds__(256) void attn_kernel() {
    extern __shared__ float smf[];
    float* sQ  = smf;
    float* sK  = sQ  + BR * AST;
    float* sVt = sK  + BC * AST;
    float* sP  = sVt + HD * AST;

    const int bh   = blockIdx.y;
    const int rblk = blockIdx.x;
    const int tid  = threadIdx.x;
    const int ty = tid >> 4, tx = tid & 15;

    const float* Qg = g_Q + (bh * SEQ + rblk * BR) * HD;
    const float* Kg = g_K + bh * SEQ * HD;
    const float* Vg = g_V + bh * SEQ * HD;

#pragma unroll
    for (int it = 0; it < 8; it++) {
        int e = tid * 4 + it * 1024;
        int r = e >> 6, d = e & 63;
        *(float4*)&sQ[r * AST + d] = *(const float4*)(Qg + r * HD + d);
    }

    float mi[8], li[8], acc[8][4];
#pragma unroll
    for (int i = 0; i < 8; i++) {
        mi[i] = -1e30f;
        li[i] = 0.0f;
#pragma unroll
        for (int j = 0; j < 4; j++) acc[i][j] = 0.0f;
    }

    for (int c0 = 0; c0 < SEQ; c0 += BC) {
        __syncthreads();
#pragma unroll
        for (int it = 0; it < 4; it++) {
            int e = tid * 4 + it * 1024;
            int r = e >> 6, d = e & 63;
            *(float4*)&sK[r * AST + d] = *(const float4*)(Kg + (c0 + r) * HD + d);
        }
        {
            const int d  = tid & 63;
            const int kb = tid >> 6;
#pragma unroll
            for (int it = 0; it < 16; it++) {
                int kv = it * 4 + kb;
                sVt[d * AST + kv] = Vg[(c0 + kv) * HD + d];
            }
        }
        __syncthreads();

        float s[8][4];
#pragma unroll
        for (int i = 0; i < 8; i++)
#pragma unroll
            for (int j = 0; j < 4; j++) s[i][j] = 0.0f;

        for (int k = 0; k < HD; k += 4) {
            float4 a[8], b[4];
#pragma unroll
            for (int i = 0; i < 8; i++) a[i] = *(const float4*)&sQ[(ty + 16 * i) * AST + k];
#pragma unroll
            for (int j = 0; j < 4; j++) b[j] = *(const float4*)&sK[(tx + 16 * j) * AST + k];
#pragma unroll
            for (int i = 0; i < 8; i++)
#pragma unroll
                for (int j = 0; j < 4; j++)
                    s[i][j] += a[i].x * b[j].x + a[i].y * b[j].y +
                               a[i].z * b[j].z + a[i].w * b[j].w;
        }

#pragma unroll
        for (int i = 0; i < 8; i++) {
            float rmax = -1e30f;
#pragma unroll
            for (int j = 0; j < 4; j++) {
                s[i][j] *= 0.125f;
                rmax = fmaxf(rmax, s[i][j]);
            }
#pragma unroll
            for (int off = 8; off > 0; off >>= 1)
                rmax = fmaxf(rmax, __shfl_xor_sync(0xffffffffu, rmax, off, 16));
            float mn = fmaxf(mi[i], rmax);
            float rsum = 0.0f;
#pragma unroll
            for (int j = 0; j < 4; j++) {
                s[i][j] = __expf(s[i][j] - mn);
                rsum += s[i][j];
            }
#pragma unroll
            for (int off = 8; off > 0; off >>= 1)
                rsum += __shfl_xor_sync(0xffffffffu, rsum, off, 16);
            float alpha = __expf(mi[i] - mn);
            li[i] = li[i] * alpha + rsum;
            mi[i] = mn;
#pragma unroll
            for (int j = 0; j < 4; j++) acc[i][j] *= alpha;
        }

#pragma unroll
        for (int i = 0; i < 8; i++)
#pragma unroll
            for (int j = 0; j < 4; j++)
                sP[(ty + 16 * i) * AST + tx + 16 * j] = s[i][j];
        __syncthreads();

        for (int k = 0; k < BC; k += 4) {
            float4 a[8], b[4];
#pragma unroll
            for (int i = 0; i < 8; i++) a[i] = *(const float4*)&sP[(ty + 16 * i) * AST + k];
#pragma unroll
            for (int j = 0; j < 4; j++) b[j] = *(const float4*)&sVt[(tx + 16 * j) * AST + k];
#pragma unroll
            for (int i = 0; i < 8; i++)
#pragma unroll
                for (int j = 0; j < 4; j++)
                    acc[i][j] += a[i].x * b[j].x + a[i].y * b[j].y +
                                 a[i].z * b[j].z + a[i].w * b[j].w;
        }
    }

    float* Og = g_O + (bh * SEQ + rblk * BR) * HD;
#pragma unroll
    for (int i = 0; i < 8; i++) {
        const float inv = 1.0f / li[i];
        const int r = ty + 16 * i;
#pragma unroll
        for (int j = 0; j < 4; j++)
            Og[r * HD + tx + 16 * j] = acc[i][j] * inv;
    }
}

// ---------------------------------------------------------------------------

extern "C" void kernel_launch(void* const* d_in, const int* in_sizes, int n_in,
                              void* d_out, int out_size) {
    (void)in_sizes; (void)n_in; (void)out_size;
    const float* x  = (const float*)d_in[0];
    const float* Wq = (const float*)d_in[1];
    const float* Wk = (const float*)d_in[2];
    const float* Wv = (const float*)d_in[3];
    const float* Wo = (const float*)d_in[4];
    const float* bo = (const float*)d_in[5];
    float* out = (float*)d_out;

    const int attn_smem = (BR + BC + HD + BR) * AST * (int)sizeof(float);
    cudaFuncSetAttribute(attn_kernel, cudaFuncAttributeMaxDynamicSharedMemorySize, attn_smem);
    cudaFuncSetAttribute(gemm_mma<0>, cudaFuncAttributeMaxDynamicSharedMemorySize, GSM_BYTES);
    cudaFuncSetAttribute(gemm_mma<1>, cudaFuncAttributeMaxDynamicSharedMemorySize, GSM_BYTES);

    __nv_bfloat16 *wh, *wl, *woh, *wol, *xh, *xl, *oh, *ol;
    cudaGetSymbolAddress((void**)&wh,  g_wh);
    cudaGetSymbolAddress((void**)&wl,  g_wl);
    cudaGetSymbolAddress((void**)&woh, g_woh);
    cudaGetSymbolAddress((void**)&wol, g_wol);
    cudaGetSymbolAddress((void**)&xh,  g_xh);
    cudaGetSymbolAddress((void**)&xl,  g_xl);
    cudaGetSymbolAddress((void**)&oh,  g_oh);
    cudaGetSymbolAddress((void**)&ol,  g_ol);

    split_x_kernel<<<MROWS * DIM / 1024, 256>>>(x);
    dim3 tgrid(32, 32), tblk(32, 8);
    transpose_split_kernel<<<tgrid, tblk>>>(Wq, wh,                 wl);
    transpose_split_kernel<<<tgrid, tblk>>>(Wk, wh + DIM * DIM,     wl + DIM * DIM);
    transpose_split_kernel<<<tgrid, tblk>>>(Wv, wh + 2 * DIM * DIM, wl + 2 * DIM * DIM);
    transpose_split_kernel<<<tgrid, tblk>>>(Wo, woh,                wol);

    gemm_mma<0><<<dim3(24, 64), 256, GSM_BYTES>>>(xh, xl, wh, wl, nullptr, nullptr);
    attn_kernel<<<dim3(16, 64), 256, attn_smem>>>();
    split_O_kernel<<<QKV_ELEMS / 1024, 256>>>();
    gemm_mma<1><<<dim3(8, 64), 256, GSM_BYTES>>>(oh, ol, woh, wol, out, bo);
}

// round 4
// speedup vs baseline: 2.2872x; 1.7732x over previous
#include <cuda_runtime.h>
#include <cuda_bf16.h>
#include <cstdint>

#define DIM    1024
#define HEADS  16
#define HD     64
#define BATCH  4
#define SEQ    2048
#define MROWS  (BATCH * SEQ)            // 8192
#define QKV_ELEMS (BATCH * HEADS * SEQ * HD)  // 8388608

// ---------------------------------------------------------------------------
// Scratch (allocation-free rule: __device__ globals) — all bf16 hi/lo pairs
// ---------------------------------------------------------------------------
__device__ __nv_bfloat16 g_Qh[QKV_ELEMS], g_Ql[QKV_ELEMS];   // [b,h,n,d]
__device__ __nv_bfloat16 g_Kh[QKV_ELEMS], g_Kl[QKV_ELEMS];   // [b,h,n,d]
__device__ __nv_bfloat16 g_Vh[QKV_ELEMS], g_Vl[QKV_ELEMS];   // [b,h,d,n] (transposed)
__device__ __nv_bfloat16 g_xh[MROWS * DIM], g_xl[MROWS * DIM];
__device__ __nv_bfloat16 g_wh[3 * DIM * DIM], g_wl[3 * DIM * DIM];  // W^T [n][k]
__device__ __nv_bfloat16 g_woh[DIM * DIM], g_wol[DIM * DIM];        // Wo^T [n][k]
__device__ __nv_bfloat16 g_oh[MROWS * DIM], g_ol[MROWS * DIM];      // attn out [m][h*64+d]

// ---------------------------------------------------------------------------
// mma.sync helpers
// ---------------------------------------------------------------------------
__device__ __forceinline__ uint32_t smem_u32(const void* p) {
    uint32_t a;
    asm("{ .reg .u64 t; cvta.to.shared.u64 t, %1; cvt.u32.u64 %0, t; }" : "=r"(a) : "l"(p));
    return a;
}
__device__ __forceinline__ void ldsm4(uint32_t& r0, uint32_t& r1, uint32_t& r2, uint32_t& r3,
                                      uint32_t addr) {
    asm volatile("ldmatrix.sync.aligned.m8n8.x4.shared.b16 {%0,%1,%2,%3}, [%4];"
                 : "=r"(r0), "=r"(r1), "=r"(r2), "=r"(r3) : "r"(addr));
}
__device__ __forceinline__ void mma16816(float* d, const uint32_t* a, const uint32_t* b) {
    asm volatile(
        "mma.sync.aligned.m16n8k16.row.col.f32.bf16.bf16.f32 "
        "{%0,%1,%2,%3}, {%4,%5,%6,%7}, {%8,%9}, {%0,%1,%2,%3};"
        : "+f"(d[0]), "+f"(d[1]), "+f"(d[2]), "+f"(d[3])
        : "r"(a[0]), "r"(a[1]), "r"(a[2]), "r"(a[3]), "r"(b[0]), "r"(b[1]));
}
__device__ __forceinline__ void split2(float v, __nv_bfloat16& h, __nv_bfloat16& l) {
    h = __float2bfloat16(v);
    l = __float2bfloat16(v - __bfloat162float(h));
}

// ---------------------------------------------------------------------------
// Prep kernels
// ---------------------------------------------------------------------------
__global__ __launch_bounds__(256) void split_x_kernel(const float* __restrict__ x) {
    int i = (blockIdx.x * 256 + threadIdx.x) * 4;
    float4 v = *(const float4*)(x + i);
    __nv_bfloat16 h0, h1, h2, h3, l0, l1, l2, l3;
    split2(v.x, h0, l0); split2(v.y, h1, l1); split2(v.z, h2, l2); split2(v.w, h3, l3);
    *(__nv_bfloat162*)(g_xh + i)     = {h0, h1};
    *(__nv_bfloat162*)(g_xh + i + 2) = {h2, h3};
    *(__nv_bfloat162*)(g_xl + i)     = {l0, l1};
    *(__nv_bfloat162*)(g_xl + i + 2) = {l2, l3};
}

__global__ __launch_bounds__(256) void transpose_split_kernel(const float* __restrict__ src,
                                                              __nv_bfloat16* __restrict__ dh,
                                                              __nv_bfloat16* __restrict__ dl) {
    __shared__ float t[32][33];
    const int bx = blockIdx.x * 32;   // n base
    const int by = blockIdx.y * 32;   // k base
    const int x = threadIdx.x, y0 = threadIdx.y;  // block (32,8)
#pragma unroll
    for (int i = 0; i < 32; i += 8)
        t[y0 + i][x] = src[(by + y0 + i) * DIM + bx + x];
    __syncthreads();
#pragma unroll
    for (int i = 0; i < 32; i += 8) {
        float v = t[x][y0 + i];
        __nv_bfloat16 h, l; split2(v, h, l);
        int o = (bx + y0 + i) * DIM + by + x;
        dh[o] = h; dl[o] = l;
    }
}

// ---------------------------------------------------------------------------
// bf16x3 split GEMM on mma.sync (proven R3 core).
// MODE 0: QKV -> bf16 hi/lo Q/K ([b,h,n,d]) and V^T ([b,h,d,n])
// MODE 1: out proj + bias -> d_out (fp32)
// ---------------------------------------------------------------------------
#define GBK   64
#define GSTR  72
#define GARR  (128 * GSTR)
#define GSM_BYTES (4 * GARR * 2)   // 73728

template <int MODE>
__global__ __launch_bounds__(256) void gemm_mma(
    const __nv_bfloat16* __restrict__ Ah, const __nv_bfloat16* __restrict__ Al,
    const __nv_bfloat16* __restrict__ Bh, const __nv_bfloat16* __restrict__ Bl,
    float* __restrict__ outp, const float* __restrict__ bo) {
    extern __shared__ __nv_bfloat16 sm[];
    __nv_bfloat16* SAh = sm;
    __nv_bfloat16* SAl = sm + GARR;
    __nv_bfloat16* SBh = sm + 2 * GARR;
    __nv_bfloat16* SBl = sm + 3 * GARR;

    const int tid  = threadIdx.x;
    const int lane = tid & 31;
    const int wid  = tid >> 5;
    const int wm   = wid & 1;
    const int wn   = wid >> 1;
    const int row0 = blockIdx.y * 128;
    const int col0 = blockIdx.x * 128;

    const __nv_bfloat16* pAh = Ah + (size_t)row0 * DIM;
    const __nv_bfloat16* pAl = Al + (size_t)row0 * DIM;
    const __nv_bfloat16* pBh = Bh + (size_t)col0 * DIM;
    const __nv_bfloat16* pBl = Bl + (size_t)col0 * DIM;

    const uint32_t sAh = smem_u32(SAh), sAl = smem_u32(SAl);
    const uint32_t sBh = smem_u32(SBh), sBl = smem_u32(SBl);

    float acc[4][4][4];
#pragma unroll
    for (int i = 0; i < 4; i++)
#pragma unroll
        for (int j = 0; j < 4; j++)
#pragma unroll
            for (int q = 0; q < 4; q++) acc[i][j][q] = 0.0f;

    const int a_row = (lane & 15);
    const int a_kof = (lane >> 4) << 3;
    const int b_rof = ((lane >> 4) << 3) + (lane & 7);
    const int b_kof = ((lane >> 3) & 1) << 3;

    for (int c = 0; c < DIM / GBK; ++c) {
        if (c) __syncthreads();
        const int k0 = c * GBK;
#pragma unroll
        for (int it = 0; it < 4; ++it) {
            const int lin = it * 256 + tid;
            const int r  = lin >> 3;
            const int cg = (lin & 7) * 8;
            const int so = r * GSTR + cg;
            const size_t go = (size_t)r * DIM + k0 + cg;
            *(uint4*)(SAh + so) = *(const uint4*)(pAh + go);
            *(uint4*)(SAl + so) = *(const uint4*)(pAl + go);
            *(uint4*)(SBh + so) = *(const uint4*)(pBh + go);
            *(uint4*)(SBl + so) = *(const uint4*)(pBl + go);
        }
        __syncthreads();

#pragma unroll
        for (int ks = 0; ks < GBK / 16; ++ks) {
            uint32_t ah[4][4], al[4][4], bh[2][4], bl[2][4];
#pragma unroll
            for (int mi = 0; mi < 4; ++mi) {
                const uint32_t off =
                    (uint32_t)(((wm * 64 + mi * 16 + a_row) * GSTR + ks * 16 + a_kof) * 2);
                ldsm4(ah[mi][0], ah[mi][1], ah[mi][2], ah[mi][3], sAh + off);
                ldsm4(al[mi][0], al[mi][1], al[mi][2], al[mi][3], sAl + off);
            }
#pragma unroll
            for (int p = 0; p < 2; ++p) {
                const uint32_t off =
                    (uint32_t)(((wn * 32 + p * 16 + b_rof) * GSTR + ks * 16 + b_kof) * 2);
                ldsm4(bh[p][0], bh[p][1], bh[p][2], bh[p][3], sBh + off);
                ldsm4(bl[p][0], bl[p][1], bl[p][2], bl[p][3], sBl + off);
            }
#pragma unroll
            for (int mi = 0; mi < 4; ++mi)
#pragma unroll
                for (int p = 0; p < 2; ++p)
#pragma unroll
                    for (int q = 0; q < 2; ++q) {
                        float* d = acc[mi][p * 2 + q];
                        mma16816(d, ah[mi], &bh[p][q * 2]);
                        mma16816(d, ah[mi], &bl[p][q * 2]);
                        mma16816(d, al[mi], &bh[p][q * 2]);
                    }
        }
    }

#pragma unroll
    for (int mi = 0; mi < 4; ++mi) {
#pragma unroll
        for (int nj = 0; nj < 4; ++nj) {
            const int r = row0 + wm * 64 + mi * 16 + (lane >> 2);
            const int cgl = col0 + wn * 32 + nj * 8 + (lane & 3) * 2;
#pragma unroll
            for (int half = 0; half < 2; ++half) {
                const int rr = r + half * 8;
                const float v0 = acc[mi][nj][half * 2 + 0];
                const float v1 = acc[mi][nj][half * 2 + 1];
                if (MODE == 0) {
                    const int b_ = rr >> 11, n = rr & 2047;
                    const int wsel = cgl >> 10;
                    const int c1 = cgl & 1023;
                    const int h = c1 >> 6, d0 = c1 & 63;
                    __nv_bfloat16 h0, l0, h1, l1;
                    split2(v0, h0, l0); split2(v1, h1, l1);
                    if (wsel < 2) {
                        __nv_bfloat16* dh = wsel ? g_Kh : g_Qh;
                        __nv_bfloat16* dl = wsel ? g_Kl : g_Ql;
                        const size_t o = ((size_t)(b_ * HEADS + h) * SEQ + n) * HD + d0;
                        *(__nv_bfloat162*)(dh + o) = {h0, h1};
                        *(__nv_bfloat162*)(dl + o) = {l0, l1};
                    } else {
                        const size_t o = ((size_t)(b_ * HEADS + h) * HD + d0) * SEQ + n;
                        g_Vh[o] = h0; g_Vh[o + SEQ] = h1;
                        g_Vl[o] = l0; g_Vl[o + SEQ] = l1;
                    }
                } else {
                    *(float2*)(outp + (size_t)rr * DIM + cgl) =
                        make_float2(v0 + bo[cgl], v1 + bo[cgl + 1]);
                }
            }
        }
    }
}

// ---------------------------------------------------------------------------
// Flash attention on mma.sync, bf16x3 split for QK^T and PV.
// One block per (b*h, 128 q rows). 8 warps, each owns 16 rows x full 64 cols.
// ---------------------------------------------------------------------------
#define ASTR 72
#define A_QH 0
#define A_QL (128 * ASTR)          // 9216
#define A_KH (2 * 128 * ASTR)      // 18432
#define A_KL (A_KH + 64 * ASTR)
#define A_VH (A_KL + 64 * ASTR)
#define A_VL (A_VH + 64 * ASTR)
#define A_PH (A_VL + 64 * ASTR)    // 36864
#define A_PL (A_PH + 128 * ASTR)
#define A_TOTAL ((A_PL + 128 * ASTR) * 2)   // bytes = 110592

__global__ __launch_bounds__(256) void attn_mma() {
    extern __shared__ __nv_bfloat16 sma[];
    __nv_bfloat16* sQh = sma + A_QH;
    __nv_bfloat16* sQl = sma + A_QL;
    __nv_bfloat16* sKh = sma + A_KH;
    __nv_bfloat16* sKl = sma + A_KL;
    __nv_bfloat16* sVh = sma + A_VH;
    __nv_bfloat16* sVl = sma + A_VL;
    __nv_bfloat16* sPh = sma + A_PH;
    __nv_bfloat16* sPl = sma + A_PL;

    const int bh   = blockIdx.y;
    const int rblk = blockIdx.x;
    const int tid  = threadIdx.x;
    const int lane = tid & 31;
    const int wid  = tid >> 5;
    const int q0   = wid * 16;

    const size_t qbase = ((size_t)bh * SEQ + rblk * 128) * HD;
    const size_t kbase = (size_t)bh * SEQ * HD;
    const size_t vbase = (size_t)bh * HD * SEQ;

    // Load Q tile 128x64 (hi & lo)
#pragma unroll
    for (int it = 0; it < 4; ++it) {
        const int lin = it * 256 + tid;
        const int r = lin >> 3, d = (lin & 7) * 8;
        *(uint4*)(sQh + r * ASTR + d) = *(const uint4*)(g_Qh + qbase + r * HD + d);
        *(uint4*)(sQl + r * ASTR + d) = *(const uint4*)(g_Ql + qbase + r * HD + d);
    }

    float acc_o[8][4];
#pragma unroll
    for (int j = 0; j < 8; j++)
#pragma unroll
        for (int q = 0; q < 4; q++) acc_o[j][q] = 0.0f;
    float mi[2] = {-1e30f, -1e30f}, li[2] = {0.0f, 0.0f};

    const int a_row = lane & 15;
    const int a_kof = (lane >> 4) << 3;
    const int b_rof = ((lane >> 4) << 3) + (lane & 7);
    const int b_kof = ((lane >> 3) & 1) << 3;

    const uint32_t uQh = smem_u32(sQh), uQl = smem_u32(sQl);
    const uint32_t uKh = smem_u32(sKh), uKl = smem_u32(sKl);
    const uint32_t uVh = smem_u32(sVh), uVl = smem_u32(sVl);
    const uint32_t uPh = smem_u32(sPh), uPl = smem_u32(sPl);

    for (int c0 = 0; c0 < SEQ; c0 += 64) {
        __syncthreads();   // prior PV smem reads complete
        // Load K chunk [kv 64][d 64] and V^T chunk [d 64][kv 64]
#pragma unroll
        for (int it = 0; it < 2; ++it) {
            const int lin = it * 256 + tid;
            const int r = lin >> 3, d = (lin & 7) * 8;
            *(uint4*)(sKh + r * ASTR + d) = *(const uint4*)(g_Kh + kbase + (size_t)(c0 + r) * HD + d);
            *(uint4*)(sKl + r * ASTR + d) = *(const uint4*)(g_Kl + kbase + (size_t)(c0 + r) * HD + d);
            *(uint4*)(sVh + r * ASTR + d) = *(const uint4*)(g_Vh + vbase + (size_t)r * SEQ + c0 + d);
            *(uint4*)(sVl + r * ASTR + d) = *(const uint4*)(g_Vl + vbase + (size_t)r * SEQ + c0 + d);
        }
        __syncthreads();

        // S = Q K^T : warp rows q0..q0+15, cols 0..63
        float acc_s[8][4];
#pragma unroll
        for (int j = 0; j < 8; j++)
#pragma unroll
            for (int q = 0; q < 4; q++) acc_s[j][q] = 0.0f;

#pragma unroll
        for (int ks = 0; ks < 4; ++ks) {
            uint32_t ah[4], al[4];
            {
                const uint32_t off = (uint32_t)(((q0 + a_row) * ASTR + ks * 16 + a_kof) * 2);
                ldsm4(ah[0], ah[1], ah[2], ah[3], uQh + off);
                ldsm4(al[0], al[1], al[2], al[3], uQl + off);
            }
#pragma unroll
            for (int p = 0; p < 4; ++p) {
                uint32_t bh_[4], bl_[4];
                const uint32_t off = (uint32_t)(((p * 16 + b_rof) * ASTR + ks * 16 + b_kof) * 2);
                ldsm4(bh_[0], bh_[1], bh_[2], bh_[3], uKh + off);
                ldsm4(bl_[0], bl_[1], bl_[2], bl_[3], uKl + off);
#pragma unroll
                for (int q = 0; q < 2; ++q) {
                    float* d = acc_s[p * 2 + q];
                    mma16816(d, ah, &bh_[q * 2]);
                    mma16816(d, ah, &bl_[q * 2]);
                    mma16816(d, al, &bh_[q * 2]);
                }
            }
        }

        // Online softmax, two rows per thread (half 0: r, half 1: r+8)
#pragma unroll
        for (int half = 0; half < 2; ++half) {
            float rmax = -1e30f;
#pragma unroll
            for (int nj = 0; nj < 8; ++nj)
#pragma unroll
                for (int t = 0; t < 2; ++t) {
                    acc_s[nj][half * 2 + t] *= 0.125f;
                    rmax = fmaxf(rmax, acc_s[nj][half * 2 + t]);
                }
            rmax = fmaxf(rmax, __shfl_xor_sync(0xffffffffu, rmax, 1));
            rmax = fmaxf(rmax, __shfl_xor_sync(0xffffffffu, rmax, 2));
            const float mn = fmaxf(mi[half], rmax);
            float rsum = 0.0f;
#pragma unroll
            for (int nj = 0; nj < 8; ++nj)
#pragma unroll
                for (int t = 0; t < 2; ++t) {
                    const float e = __expf(acc_s[nj][half * 2 + t] - mn);
                    acc_s[nj][half * 2 + t] = e;
                    rsum += e;
                }
            rsum += __shfl_xor_sync(0xffffffffu, rsum, 1);
            rsum += __shfl_xor_sync(0xffffffffu, rsum, 2);
            const float alpha = __expf(mi[half] - mn);
            li[half] = li[half] * alpha + rsum;
            mi[half] = mn;
#pragma unroll
            for (int nj = 0; nj < 8; ++nj)
#pragma unroll
                for (int t = 0; t < 2; ++t) acc_o[nj][half * 2 + t] *= alpha;

            // publish P (bf16 hi/lo)
            const int row = q0 + (lane >> 2) + half * 8;
#pragma unroll
            for (int nj = 0; nj < 8; ++nj) {
                const float p0 = acc_s[nj][half * 2 + 0];
                const float p1 = acc_s[nj][half * 2 + 1];
                __nv_bfloat16 h0, l0, h1, l1;
                split2(p0, h0, l0); split2(p1, h1, l1);
                const int cc = nj * 8 + (lane & 3) * 2;
                *(__nv_bfloat162*)(sPh + row * ASTR + cc) = {h0, h1};
                *(__nv_bfloat162*)(sPl + row * ASTR + cc) = {l0, l1};
            }
        }
        __syncthreads();

        // O += P V : A = P [row][kv], B = V^T [d][kv]
#pragma unroll
        for (int ks = 0; ks < 4; ++ks) {
            uint32_t ah[4], al[4];
            {
                const uint32_t off = (uint32_t)(((q0 + a_row) * ASTR + ks * 16 + a_kof) * 2);
                ldsm4(ah[0], ah[1], ah[2], ah[3], uPh + off);
                ldsm4(al[0], al[1], al[2], al[3], uPl + off);
            }
#pragma unroll
            for (int p = 0; p < 4; ++p) {
                uint32_t bh_[4], bl_[4];
                const uint32_t off = (uint32_t)(((p * 16 + b_rof) * ASTR + ks * 16 + b_kof) * 2);
                ldsm4(bh_[0], bh_[1], bh_[2], bh_[3], uVh + off);
                ldsm4(bl_[0], bl_[1], bl_[2], bl_[3], uVl + off);
#pragma unroll
                for (int q = 0; q < 2; ++q) {
                    float* d = acc_o[p * 2 + q];
                    mma16816(d, ah, &bh_[q * 2]);
                    mma16816(d, ah, &bl_[q * 2]);
                    mma16816(d, al, &bh_[q * 2]);
                }
            }
        }
    }

    // Epilogue: normalize, split bf16 hi/lo, write to proj-GEMM A layout
    const int b_ = bh >> 4, h = bh & 15;
#pragma unroll
    for (int half = 0; half < 2; ++half) {
        const float inv = 1.0f / li[half];
        const int row = rblk * 128 + q0 + (lane >> 2) + half * 8;
        const size_t mrow = ((size_t)b_ * SEQ + row) * DIM + h * HD;
#pragma unroll
        for (int nj = 0; nj < 8; ++nj) {
            const float o0 = acc_o[nj][half * 2 + 0] * inv;
            const float o1 = acc_o[nj][half * 2 + 1] * inv;
            __nv_bfloat16 h0, l0, h1, l1;
            split2(o0, h0, l0); split2(o1, h1, l1);
            const int cc = nj * 8 + (lane & 3) * 2;
            *(__nv_bfloat162*)(g_oh + mrow + cc) = {h0, h1};
            *(__nv_bfloat162*)(g_ol + mrow + cc) = {l0, l1};
        }
    }
}

// ---------------------------------------------------------------------------

extern "C" void kernel_launch(void* const* d_in, const int* in_sizes, int n_in,
                              void* d_out, int out_size) {
    (void)in_sizes; (void)n_in; (void)out_size;
    const float* x  = (const float*)d_in[0];
    const float* Wq = (const float*)d_in[1];
    const float* Wk = (const float*)d_in[2];
    const float* Wv = (const float*)d_in[3];
    const float* Wo = (const float*)d_in[4];
    const float* bo = (const float*)d_in[5];
    float* out = (float*)d_out;

    cudaFuncSetAttribute(gemm_mma<0>, cudaFuncAttributeMaxDynamicSharedMemorySize, GSM_BYTES);
    cudaFuncSetAttribute(gemm_mma<1>, cudaFuncAttributeMaxDynamicSharedMemorySize, GSM_BYTES);
    cudaFuncSetAttribute(attn_mma,    cudaFuncAttributeMaxDynamicSharedMemorySize, A_TOTAL);

    __nv_bfloat16 *wh, *wl, *woh, *wol, *xh, *xl, *oh, *ol;
    cudaGetSymbolAddress((void**)&wh,  g_wh);
    cudaGetSymbolAddress((void**)&wl,  g_wl);
    cudaGetSymbolAddress((void**)&woh, g_woh);
    cudaGetSymbolAddress((void**)&wol, g_wol);
    cudaGetSymbolAddress((void**)&xh,  g_xh);
    cudaGetSymbolAddress((void**)&xl,  g_xl);
    cudaGetSymbolAddress((void**)&oh,  g_oh);
    cudaGetSymbolAddress((void**)&ol,  g_ol);

    split_x_kernel<<<MROWS * DIM / 1024, 256>>>(x);
    dim3 tgrid(32, 32), tblk(32, 8);
    transpose_split_kernel<<<tgrid, tblk>>>(Wq, wh,                 wl);
    transpose_split_kernel<<<tgrid, tblk>>>(Wk, wh + DIM * DIM,     wl + DIM * DIM);
    transpose_split_kernel<<<tgrid, tblk>>>(Wv, wh + 2 * DIM * DIM, wl + 2 * DIM * DIM);
    transpose_split_kernel<<<tgrid, tblk>>>(Wo, woh,                wol);

    gemm_mma<0><<<dim3(24, 64), 256, GSM_BYTES>>>(xh, xl, wh, wl, nullptr, nullptr);
    attn_mma<<<dim3(16, 64), 256, A_TOTAL>>>();
    gemm_mma<1><<<dim3(8, 64), 256, GSM_BYTES>>>(oh, ol, woh, wol, out, bo);
}

// round 5
// speedup vs baseline: 2.3964x; 1.0478x over previous
#include <cuda_runtime.h>
#include <cuda_bf16.h>
#include <cstdint>

#define DIM    1024
#define HEADS  16
#define HD     64
#define BATCH  4
#define SEQ    2048
#define MROWS  (BATCH * SEQ)            // 8192
#define QKV_ELEMS (BATCH * HEADS * SEQ * HD)  // 8388608

// ---------------------------------------------------------------------------
// Scratch (allocation-free rule: __device__ globals) — all bf16 hi/lo pairs
// ---------------------------------------------------------------------------
__device__ __nv_bfloat16 g_Qh[QKV_ELEMS], g_Ql[QKV_ELEMS];   // [b,h,n,d]
__device__ __nv_bfloat16 g_Kh[QKV_ELEMS], g_Kl[QKV_ELEMS];   // [b,h,n,d]
__device__ __nv_bfloat16 g_Vh[QKV_ELEMS], g_Vl[QKV_ELEMS];   // [b,h,d,n] (transposed)
__device__ __nv_bfloat16 g_xh[MROWS * DIM], g_xl[MROWS * DIM];
__device__ __nv_bfloat16 g_wh[3 * DIM * DIM], g_wl[3 * DIM * DIM];  // W^T [n][k]
__device__ __nv_bfloat16 g_woh[DIM * DIM], g_wol[DIM * DIM];        // Wo^T [n][k]
__device__ __nv_bfloat16 g_oh[MROWS * DIM], g_ol[MROWS * DIM];      // attn out [m][h*64+d]

// ---------------------------------------------------------------------------
// helpers
// ---------------------------------------------------------------------------
__device__ __forceinline__ uint32_t smem_u32(const void* p) {
    uint32_t a;
    asm("{ .reg .u64 t; cvta.to.shared.u64 t, %1; cvt.u32.u64 %0, t; }" : "=r"(a) : "l"(p));
    return a;
}
__device__ __forceinline__ void ldsm4(uint32_t& r0, uint32_t& r1, uint32_t& r2, uint32_t& r3,
                                      uint32_t addr) {
    asm volatile("ldmatrix.sync.aligned.m8n8.x4.shared.b16 {%0,%1,%2,%3}, [%4];"
                 : "=r"(r0), "=r"(r1), "=r"(r2), "=r"(r3) : "r"(addr));
}
__device__ __forceinline__ void mma16816(float* d, const uint32_t* a, const uint32_t* b) {
    asm volatile(
        "mma.sync.aligned.m16n8k16.row.col.f32.bf16.bf16.f32 "
        "{%0,%1,%2,%3}, {%4,%5,%6,%7}, {%8,%9}, {%0,%1,%2,%3};"
        : "+f"(d[0]), "+f"(d[1]), "+f"(d[2]), "+f"(d[3])
        : "r"(a[0]), "r"(a[1]), "r"(a[2]), "r"(a[3]), "r"(b[0]), "r"(b[1]));
}
__device__ __forceinline__ void cp16(uint32_t saddr, const void* gptr) {
    asm volatile("cp.async.cg.shared.global [%0], [%1], 16;" :: "r"(saddr), "l"(gptr));
}
__device__ __forceinline__ void cp_commit() {
    asm volatile("cp.async.commit_group;" ::: "memory");
}
__device__ __forceinline__ void cp_wait0() {
    asm volatile("cp.async.wait_group 0;" ::: "memory");
}
__device__ __forceinline__ void split2(float v, __nv_bfloat16& h, __nv_bfloat16& l) {
    h = __float2bfloat16(v);
    l = __float2bfloat16(v - __bfloat162float(h));
}

// ---------------------------------------------------------------------------
// Prep kernels
// ---------------------------------------------------------------------------
__global__ __launch_bounds__(256) void split_x_kernel(const float* __restrict__ x) {
    int i = (blockIdx.x * 256 + threadIdx.x) * 4;
    float4 v = *(const float4*)(x + i);
    __nv_bfloat16 h0, h1, h2, h3, l0, l1, l2, l3;
    split2(v.x, h0, l0); split2(v.y, h1, l1); split2(v.z, h2, l2); split2(v.w, h3, l3);
    *(__nv_bfloat162*)(g_xh + i)     = {h0, h1};
    *(__nv_bfloat162*)(g_xh + i + 2) = {h2, h3};
    *(__nv_bfloat162*)(g_xl + i)     = {l0, l1};
    *(__nv_bfloat162*)(g_xl + i + 2) = {l2, l3};
}

__global__ __launch_bounds__(256) void transpose_split_kernel(const float* __restrict__ src,
                                                              __nv_bfloat16* __restrict__ dh,
                                                              __nv_bfloat16* __restrict__ dl) {
    __shared__ float t[32][33];
    const int bx = blockIdx.x * 32;   // n base
    const int by = blockIdx.y * 32;   // k base
    const int x = threadIdx.x, y0 = threadIdx.y;  // block (32,8)
#pragma unroll
    for (int i = 0; i < 32; i += 8)
        t[y0 + i][x] = src[(by + y0 + i) * DIM + bx + x];
    __syncthreads();
#pragma unroll
    for (int i = 0; i < 32; i += 8) {
        float v = t[x][y0 + i];
        __nv_bfloat16 h, l; split2(v, h, l);
        int o = (bx + y0 + i) * DIM + by + x;
        dh[o] = h; dl[o] = l;
    }
}

// ---------------------------------------------------------------------------
// bf16x3 split GEMM, cp.async 2-stage pipeline.
// MODE 0: QKV -> bf16 hi/lo Q/K ([b,h,n,d]) and V^T ([b,h,d,n])
// MODE 1: out proj + bias -> d_out (fp32)
// ---------------------------------------------------------------------------
#define GBK    64
#define GSTR   72
#define GARR   (128 * GSTR)            // elems per array (9216)
#define GSTAGE (4 * GARR)              // elems per stage (36864)
#define GSM_BYTES (2 * GSTAGE * 2)     // 147456

template <int MODE>
__global__ __launch_bounds__(256) void gemm_mma(
    const __nv_bfloat16* __restrict__ Ah, const __nv_bfloat16* __restrict__ Al,
    const __nv_bfloat16* __restrict__ Bh, const __nv_bfloat16* __restrict__ Bl,
    float* __restrict__ outp, const float* __restrict__ bo) {
    extern __shared__ __nv_bfloat16 sm[];

    const int tid  = threadIdx.x;
    const int lane = tid & 31;
    const int wid  = tid >> 5;
    const int wm   = wid & 1;
    const int wn   = wid >> 1;
    const int row0 = blockIdx.y * 128;
    const int col0 = blockIdx.x * 128;

    const __nv_bfloat16* pAh = Ah + (size_t)row0 * DIM;
    const __nv_bfloat16* pAl = Al + (size_t)row0 * DIM;
    const __nv_bfloat16* pBh = Bh + (size_t)col0 * DIM;
    const __nv_bfloat16* pBl = Bl + (size_t)col0 * DIM;

    const uint32_t sbase = smem_u32(sm);

    float acc[4][4][4];
#pragma unroll
    for (int i = 0; i < 4; i++)
#pragma unroll
        for (int j = 0; j < 4; j++)
#pragma unroll
            for (int q = 0; q < 4; q++) acc[i][j][q] = 0.0f;

    const int a_row = (lane & 15);
    const int a_kof = (lane >> 4) << 3;
    const int b_rof = ((lane >> 4) << 3) + (lane & 7);
    const int b_kof = ((lane >> 3) & 1) << 3;

    // issue one chunk's loads into stage st
    auto issue = [&](int c, int st) {
        const int k0 = c * GBK;
        const uint32_t sst = sbase + (uint32_t)(st * GSTAGE) * 2;
#pragma unroll
        for (int it = 0; it < 4; ++it) {
            const int lin = it * 256 + tid;
            const int r  = lin >> 3;
            const int cg = (lin & 7) * 8;
            const uint32_t so = (uint32_t)(r * GSTR + cg) * 2;
            const size_t go = (size_t)r * DIM + k0 + cg;
            cp16(sst + so,                       pAh + go);
            cp16(sst + (uint32_t)GARR * 2 + so,  pAl + go);
            cp16(sst + (uint32_t)(2 * GARR) * 2 + so, pBh + go);
            cp16(sst + (uint32_t)(3 * GARR) * 2 + so, pBl + go);
        }
        cp_commit();
    };

    issue(0, 0);

    const int NC = DIM / GBK;   // 16
    for (int c = 0; c < NC; ++c) {
        const int st = c & 1;
        cp_wait0();
        __syncthreads();
        if (c + 1 < NC) issue(c + 1, st ^ 1);

        const uint32_t sA = sbase + (uint32_t)(st * GSTAGE) * 2;
        const uint32_t sAh = sA;
        const uint32_t sAl = sA + (uint32_t)GARR * 2;
        const uint32_t sBh = sA + (uint32_t)(2 * GARR) * 2;
        const uint32_t sBl = sA + (uint32_t)(3 * GARR) * 2;

#pragma unroll
        for (int ks = 0; ks < GBK / 16; ++ks) {
            uint32_t ah[4][4], al[4][4], bh[2][4], bl[2][4];
#pragma unroll
            for (int mi = 0; mi < 4; ++mi) {
                const uint32_t off =
                    (uint32_t)(((wm * 64 + mi * 16 + a_row) * GSTR + ks * 16 + a_kof) * 2);
                ldsm4(ah[mi][0], ah[mi][1], ah[mi][2], ah[mi][3], sAh + off);
                ldsm4(al[mi][0], al[mi][1], al[mi][2], al[mi][3], sAl + off);
            }
#pragma unroll
            for (int p = 0; p < 2; ++p) {
                const uint32_t off =
                    (uint32_t)(((wn * 32 + p * 16 + b_rof) * GSTR + ks * 16 + b_kof) * 2);
                ldsm4(bh[p][0], bh[p][1], bh[p][2], bh[p][3], sBh + off);
                ldsm4(bl[p][0], bl[p][1], bl[p][2], bl[p][3], sBl + off);
            }
#pragma unroll
            for (int mi = 0; mi < 4; ++mi)
#pragma unroll
                for (int p = 0; p < 2; ++p)
#pragma unroll
                    for (int q = 0; q < 2; ++q) {
                        float* d = acc[mi][p * 2 + q];
                        mma16816(d, ah[mi], &bh[p][q * 2]);
                        mma16816(d, ah[mi], &bl[p][q * 2]);
                        mma16816(d, al[mi], &bh[p][q * 2]);
                    }
        }
    }

#pragma unroll
    for (int mi = 0; mi < 4; ++mi) {
#pragma unroll
        for (int nj = 0; nj < 4; ++nj) {
            const int r = row0 + wm * 64 + mi * 16 + (lane >> 2);
            const int cgl = col0 + wn * 32 + nj * 8 + (lane & 3) * 2;
#pragma unroll
            for (int half = 0; half < 2; ++half) {
                const int rr = r + half * 8;
                const float v0 = acc[mi][nj][half * 2 + 0];
                const float v1 = acc[mi][nj][half * 2 + 1];
                if (MODE == 0) {
                    const int b_ = rr >> 11, n = rr & 2047;
                    const int wsel = cgl >> 10;
                    const int c1 = cgl & 1023;
                    const int h = c1 >> 6, d0 = c1 & 63;
                    __nv_bfloat16 h0, l0, h1, l1;
                    split2(v0, h0, l0); split2(v1, h1, l1);
                    if (wsel < 2) {
                        __nv_bfloat16* dh = wsel ? g_Kh : g_Qh;
                        __nv_bfloat16* dl = wsel ? g_Kl : g_Ql;
                        const size_t o = ((size_t)(b_ * HEADS + h) * SEQ + n) * HD + d0;
                        *(__nv_bfloat162*)(dh + o) = {h0, h1};
                        *(__nv_bfloat162*)(dl + o) = {l0, l1};
                    } else {
                        const size_t o = ((size_t)(b_ * HEADS + h) * HD + d0) * SEQ + n;
                        g_Vh[o] = h0; g_Vh[o + SEQ] = h1;
                        g_Vl[o] = l0; g_Vl[o + SEQ] = l1;
                    }
                } else {
                    *(float2*)(outp + (size_t)rr * DIM + cgl) =
                        make_float2(v0 + bo[cgl], v1 + bo[cgl + 1]);
                }
            }
        }
    }
}

// ---------------------------------------------------------------------------
// Flash attention on mma.sync, bf16x3 split, cp.async 2-stage KV pipeline.
// One block per (b*h, 128 q rows). 8 warps, each owns 16 rows x full 64 cols.
// ---------------------------------------------------------------------------
#define ASTR   72
#define AQ_ELE (128 * ASTR)            // one Q array (9216)
#define AKV_AR (64 * ASTR)             // one KV array (4608)
#define AKV_ST (4 * AKV_AR)            // one KV stage (18432)
// layout (elems): Qh 0 | Ql 9216 | stage0 18432 | stage1 36864 | Ph 55296 | Pl 64512
#define A_Q0   0
#define A_Q1   AQ_ELE
#define A_KV0  (2 * AQ_ELE)
#define A_PH   (A_KV0 + 2 * AKV_ST)
#define A_PL   (A_PH + AQ_ELE)
#define A_TOTAL ((A_PL + AQ_ELE) * 2)  // 147456 bytes

__global__ __launch_bounds__(256) void attn_mma() {
    extern __shared__ __nv_bfloat16 sma[];

    const int bh   = blockIdx.y;
    const int rblk = blockIdx.x;
    const int tid  = threadIdx.x;
    const int lane = tid & 31;
    const int wid  = tid >> 5;
    const int q0   = wid * 16;

    const size_t qbase = ((size_t)bh * SEQ + rblk * 128) * HD;
    const size_t kbase = (size_t)bh * SEQ * HD;
    const size_t vbase = (size_t)bh * HD * SEQ;

    const uint32_t sbase = smem_u32(sma);
    const uint32_t uQh = sbase;
    const uint32_t uQl = sbase + (uint32_t)A_Q1 * 2;
    const uint32_t uPh = sbase + (uint32_t)A_PH * 2;
    const uint32_t uPl = sbase + (uint32_t)A_PL * 2;

    // Load Q tile 128x64 (hi & lo) via cp.async (group 1 of many; waited below)
#pragma unroll
    for (int it = 0; it < 4; ++it) {
        const int lin = it * 256 + tid;
        const int r = lin >> 3, d = (lin & 7) * 8;
        const uint32_t so = (uint32_t)(r * ASTR + d) * 2;
        cp16(uQh + so, g_Qh + qbase + (size_t)r * HD + d);
        cp16(uQl + so, g_Ql + qbase + (size_t)r * HD + d);
    }
    cp_commit();

    auto issue_kv = [&](int chunk, int st) {
        const int c0 = chunk * 64;
        const uint32_t skv = sbase + (uint32_t)(A_KV0 + st * AKV_ST) * 2;
#pragma unroll
        for (int it = 0; it < 2; ++it) {
            const int lin = it * 256 + tid;
            const int r = lin >> 3, d = (lin & 7) * 8;
            const uint32_t so = (uint32_t)(r * ASTR + d) * 2;
            cp16(skv + so,                            g_Kh + kbase + (size_t)(c0 + r) * HD + d);
            cp16(skv + (uint32_t)AKV_AR * 2 + so,     g_Kl + kbase + (size_t)(c0 + r) * HD + d);
            cp16(skv + (uint32_t)(2 * AKV_AR) * 2 + so, g_Vh + vbase + (size_t)r * SEQ + c0 + d);
            cp16(skv + (uint32_t)(3 * AKV_AR) * 2 + so, g_Vl + vbase + (size_t)r * SEQ + c0 + d);
        }
        cp_commit();
    };

    issue_kv(0, 0);

    float acc_o[8][4];
#pragma unroll
    for (int j = 0; j < 8; j++)
#pragma unroll
        for (int q = 0; q < 4; q++) acc_o[j][q] = 0.0f;
    float mi[2] = {-1e30f, -1e30f}, li[2] = {0.0f, 0.0f};

    const int a_row = lane & 15;
    const int a_kof = (lane >> 4) << 3;
    const int b_rof = ((lane >> 4) << 3) + (lane & 7);
    const int b_kof = ((lane >> 3) & 1) << 3;

    const int NC = SEQ / 64;   // 32
    for (int c = 0; c < NC; ++c) {
        const int st = c & 1;
        cp_wait0();
        __syncthreads();
        if (c + 1 < NC) issue_kv(c + 1, st ^ 1);

        const uint32_t skv = sbase + (uint32_t)(A_KV0 + st * AKV_ST) * 2;
        const uint32_t uKh = skv;
        const uint32_t uKl = skv + (uint32_t)AKV_AR * 2;
        const uint32_t uVh = skv + (uint32_t)(2 * AKV_AR) * 2;
        const uint32_t uVl = skv + (uint32_t)(3 * AKV_AR) * 2;

        // S = Q K^T
        float acc_s[8][4];
#pragma unroll
        for (int j = 0; j < 8; j++)
#pragma unroll
            for (int q = 0; q < 4; q++) acc_s[j][q] = 0.0f;

#pragma unroll
        for (int ks = 0; ks < 4; ++ks) {
            uint32_t ah[4], al[4];
            {
                const uint32_t off = (uint32_t)(((q0 + a_row) * ASTR + ks * 16 + a_kof) * 2);
                ldsm4(ah[0], ah[1], ah[2], ah[3], uQh + off);
                ldsm4(al[0], al[1], al[2], al[3], uQl + off);
            }
#pragma unroll
            for (int p = 0; p < 4; ++p) {
                uint32_t bh_[4], bl_[4];
                const uint32_t off = (uint32_t)(((p * 16 + b_rof) * ASTR + ks * 16 + b_kof) * 2);
                ldsm4(bh_[0], bh_[1], bh_[2], bh_[3], uKh + off);
                ldsm4(bl_[0], bl_[1], bl_[2], bl_[3], uKl + off);
#pragma unroll
                for (int q = 0; q < 2; ++q) {
                    float* d = acc_s[p * 2 + q];
                    mma16816(d, ah, &bh_[q * 2]);
                    mma16816(d, ah, &bl_[q * 2]);
                    mma16816(d, al, &bh_[q * 2]);
                }
            }
        }

        // Online softmax, two rows per thread
#pragma unroll
        for (int half = 0; half < 2; ++half) {
            float rmax = -1e30f;
#pragma unroll
            for (int nj = 0; nj < 8; ++nj)
#pragma unroll
                for (int t = 0; t < 2; ++t) {
                    acc_s[nj][half * 2 + t] *= 0.125f;
                    rmax = fmaxf(rmax, acc_s[nj][half * 2 + t]);
                }
            rmax = fmaxf(rmax, __shfl_xor_sync(0xffffffffu, rmax, 1));
            rmax = fmaxf(rmax, __shfl_xor_sync(0xffffffffu, rmax, 2));
            const float mn = fmaxf(mi[half], rmax);
            float rsum = 0.0f;
#pragma unroll
            for (int nj = 0; nj < 8; ++nj)
#pragma unroll
                for (int t = 0; t < 2; ++t) {
                    const float e = __expf(acc_s[nj][half * 2 + t] - mn);
                    acc_s[nj][half * 2 + t] = e;
                    rsum += e;
                }
            rsum += __shfl_xor_sync(0xffffffffu, rsum, 1);
            rsum += __shfl_xor_sync(0xffffffffu, rsum, 2);
            const float alpha = __expf(mi[half] - mn);
            li[half] = li[half] * alpha + rsum;
            mi[half] = mn;
#pragma unroll
            for (int nj = 0; nj < 8; ++nj)
#pragma unroll
                for (int t = 0; t < 2; ++t) acc_o[nj][half * 2 + t] *= alpha;

            const int row = q0 + (lane >> 2) + half * 8;
#pragma unroll
            for (int nj = 0; nj < 8; ++nj) {
                const float p0 = acc_s[nj][half * 2 + 0];
                const float p1 = acc_s[nj][half * 2 + 1];
                __nv_bfloat16 h0, l0, h1, l1;
                split2(p0, h0, l0); split2(p1, h1, l1);
                const uint32_t cc = (uint32_t)(row * ASTR + nj * 8 + (lane & 3) * 2) * 2;
                *(__nv_bfloat162*)((char*)sma + (uPh - sbase) + cc) = {h0, h1};
                *(__nv_bfloat162*)((char*)sma + (uPl - sbase) + cc) = {l0, l1};
            }
        }
        __syncthreads();

        // O += P V
#pragma unroll
        for (int ks = 0; ks < 4; ++ks) {
            uint32_t ah[4], al[4];
            {
                const uint32_t off = (uint32_t)(((q0 + a_row) * ASTR + ks * 16 + a_kof) * 2);
                ldsm4(ah[0], ah[1], ah[2], ah[3], uPh + off);
                ldsm4(al[0], al[1], al[2], al[3], uPl + off);
            }
#pragma unroll
            for (int p = 0; p < 4; ++p) {
                uint32_t bh_[4], bl_[4];
                const uint32_t off = (uint32_t)(((p * 16 + b_rof) * ASTR + ks * 16 + b_kof) * 2);
                ldsm4(bh_[0], bh_[1], bh_[2], bh_[3], uVh + off);
                ldsm4(bl_[0], bl_[1], bl_[2], bl_[3], uVl + off);
#pragma unroll
                for (int q = 0; q < 2; ++q) {
                    float* d = acc_o[p * 2 + q];
                    mma16816(d, ah, &bh_[q * 2]);
                    mma16816(d, ah, &bl_[q * 2]);
                    mma16816(d, al, &bh_[q * 2]);
                }
            }
        }
    }

    // Epilogue
    const int b_ = bh >> 4, h = bh & 15;
#pragma unroll
    for (int half = 0; half < 2; ++half) {
        const float inv = 1.0f / li[half];
        const int row = rblk * 128 + q0 + (lane >> 2) + half * 8;
        const size_t mrow = ((size_t)b_ * SEQ + row) * DIM + h * HD;
#pragma unroll
        for (int nj = 0; nj < 8; ++nj) {
            const float o0 = acc_o[nj][half * 2 + 0] * inv;
            const float o1 = acc_o[nj][half * 2 + 1] * inv;
            __nv_bfloat16 h0, l0, h1, l1;
            split2(o0, h0, l0); split2(o1, h1, l1);
            const int cc = nj * 8 + (lane & 3) * 2;
            *(__nv_bfloat162*)(g_oh + mrow + cc) = {h0, h1};
            *(__nv_bfloat162*)(g_ol + mrow + cc) = {l0, l1};
        }
    }
}

// ---------------------------------------------------------------------------

extern "C" void kernel_launch(void* const* d_in, const int* in_sizes, int n_in,
                              void* d_out, int out_size) {
    (void)in_sizes; (void)n_in; (void)out_size;
    const float* x  = (const float*)d_in[0];
    const float* Wq = (const float*)d_in[1];
    const float* Wk = (const float*)d_in[2];
    const float* Wv = (const float*)d_in[3];
    const float* Wo = (const float*)d_in[4];
    const float* bo = (const float*)d_in[5];
    float* out = (float*)d_out;

    cudaFuncSetAttribute(gemm_mma<0>, cudaFuncAttributeMaxDynamicSharedMemorySize, GSM_BYTES);
    cudaFuncSetAttribute(gemm_mma<1>, cudaFuncAttributeMaxDynamicSharedMemorySize, GSM_BYTES);
    cudaFuncSetAttribute(attn_mma,    cudaFuncAttributeMaxDynamicSharedMemorySize, A_TOTAL);

    __nv_bfloat16 *wh, *wl, *woh, *wol, *xh, *xl, *oh, *ol;
    cudaGetSymbolAddress((void**)&wh,  g_wh);
    cudaGetSymbolAddress((void**)&wl,  g_wl);
    cudaGetSymbolAddress((void**)&woh, g_woh);
    cudaGetSymbolAddress((void**)&wol, g_wol);
    cudaGetSymbolAddress((void**)&xh,  g_xh);
    cudaGetSymbolAddress((void**)&xl,  g_xl);
    cudaGetSymbolAddress((void**)&oh,  g_oh);
    cudaGetSymbolAddress((void**)&ol,  g_ol);

    split_x_kernel<<<MROWS * DIM / 1024, 256>>>(x);
    dim3 tgrid(32, 32), tblk(32, 8);
    transpose_split_kernel<<<tgrid, tblk>>>(Wq, wh,                 wl);
    transpose_split_kernel<<<tgrid, tblk>>>(Wk, wh + DIM * DIM,     wl + DIM * DIM);
    transpose_split_kernel<<<tgrid, tblk>>>(Wv, wh + 2 * DIM * DIM, wl + 2 * DIM * DIM);
    transpose_split_kernel<<<tgrid, tblk>>>(Wo, woh,                wol);

    gemm_mma<0><<<dim3(24, 64), 256, GSM_BYTES>>>(xh, xl, wh, wl, nullptr, nullptr);
    attn_mma<<<dim3(16, 64), 256, A_TOTAL>>>();
    gemm_mma<1><<<dim3(8, 64), 256, GSM_BYTES>>>(oh, ol, woh, wol, out, bo);
}

// round 6
// speedup vs baseline: 2.7809x; 1.1604x over previous
#include <cuda_runtime.h>
#include <cuda_bf16.h>
#include <cstdint>

#define DIM    1024
#define HEADS  16
#define HD     64
#define BATCH  4
#define SEQ    2048
#define MROWS  (BATCH * SEQ)            // 8192
#define QKV_ELEMS (BATCH * HEADS * SEQ * HD)  // 8388608

// ---------------------------------------------------------------------------
// Scratch (allocation-free rule: __device__ globals) — all bf16 hi/lo pairs
// ---------------------------------------------------------------------------
__device__ __nv_bfloat16 g_Qh[QKV_ELEMS], g_Ql[QKV_ELEMS];   // [b,h,n,d]
__device__ __nv_bfloat16 g_Kh[QKV_ELEMS], g_Kl[QKV_ELEMS];   // [b,h,n,d]
__device__ __nv_bfloat16 g_Vh[QKV_ELEMS], g_Vl[QKV_ELEMS];   // [b,h,d,n] (transposed)
__device__ __nv_bfloat16 g_xh[MROWS * DIM], g_xl[MROWS * DIM];
__device__ __nv_bfloat16 g_wh[3 * DIM * DIM], g_wl[3 * DIM * DIM];  // W^T [n][k]
__device__ __nv_bfloat16 g_woh[DIM * DIM], g_wol[DIM * DIM];        // Wo^T [n][k]
__device__ __nv_bfloat16 g_oh[MROWS * DIM], g_ol[MROWS * DIM];      // attn out [m][h*64+d]

// ---------------------------------------------------------------------------
// helpers
// ---------------------------------------------------------------------------
__device__ __forceinline__ uint32_t smem_u32(const void* p) {
    uint32_t a;
    asm("{ .reg .u64 t; cvta.to.shared.u64 t, %1; cvt.u32.u64 %0, t; }" : "=r"(a) : "l"(p));
    return a;
}
__device__ __forceinline__ void ldsm4(uint32_t& r0, uint32_t& r1, uint32_t& r2, uint32_t& r3,
                                      uint32_t addr) {
    asm volatile("ldmatrix.sync.aligned.m8n8.x4.shared.b16 {%0,%1,%2,%3}, [%4];"
                 : "=r"(r0), "=r"(r1), "=r"(r2), "=r"(r3) : "r"(addr));
}
__device__ __forceinline__ void mma16816(float* d, const uint32_t* a, const uint32_t* b) {
    asm volatile(
        "mma.sync.aligned.m16n8k16.row.col.f32.bf16.bf16.f32 "
        "{%0,%1,%2,%3}, {%4,%5,%6,%7}, {%8,%9}, {%0,%1,%2,%3};"
        : "+f"(d[0]), "+f"(d[1]), "+f"(d[2]), "+f"(d[3])
        : "r"(a[0]), "r"(a[1]), "r"(a[2]), "r"(a[3]), "r"(b[0]), "r"(b[1]));
}
__device__ __forceinline__ void cp16(uint32_t saddr, const void* gptr) {
    asm volatile("cp.async.cg.shared.global [%0], [%1], 16;" :: "r"(saddr), "l"(gptr));
}
__device__ __forceinline__ void cp_commit() {
    asm volatile("cp.async.commit_group;" ::: "memory");
}
__device__ __forceinline__ void cp_wait0() {
    asm volatile("cp.async.wait_group 0;" ::: "memory");
}
__device__ __forceinline__ void split2(float v, __nv_bfloat16& h, __nv_bfloat16& l) {
    h = __float2bfloat16(v);
    l = __float2bfloat16(v - __bfloat162float(h));
}
__device__ __forceinline__ uint32_t packbf(__nv_bfloat16 a, __nv_bfloat16 b) {
    __nv_bfloat162 t = {a, b};
    return *(uint32_t*)&t;
}
// split a pair of floats into packed hi / lo bf16x2
__device__ __forceinline__ void split_pack(float v0, float v1, uint32_t& ph, uint32_t& pl) {
    __nv_bfloat16 h0, l0, h1, l1;
    split2(v0, h0, l0); split2(v1, h1, l1);
    ph = packbf(h0, h1);
    pl = packbf(l0, l1);
}

// ---------------------------------------------------------------------------
// Prep kernels
// ---------------------------------------------------------------------------
__global__ __launch_bounds__(256) void split_x_kernel(const float* __restrict__ x) {
    int i = (blockIdx.x * 256 + threadIdx.x) * 4;
    float4 v = *(const float4*)(x + i);
    __nv_bfloat16 h0, h1, h2, h3, l0, l1, l2, l3;
    split2(v.x, h0, l0); split2(v.y, h1, l1); split2(v.z, h2, l2); split2(v.w, h3, l3);
    *(__nv_bfloat162*)(g_xh + i)     = {h0, h1};
    *(__nv_bfloat162*)(g_xh + i + 2) = {h2, h3};
    *(__nv_bfloat162*)(g_xl + i)     = {l0, l1};
    *(__nv_bfloat162*)(g_xl + i + 2) = {l2, l3};
}

// z in [0,4): Wq, Wk, Wv -> g_wh/g_wl slabs; z==3: Wo -> g_woh/g_wol
__global__ __launch_bounds__(256) void transpose_split4(const float* __restrict__ W0,
                                                        const float* __restrict__ W1,
                                                        const float* __restrict__ W2,
                                                        const float* __restrict__ W3) {
    __shared__ float t[32][33];
    const int z = blockIdx.z;
    const float* src = (z == 0) ? W0 : (z == 1) ? W1 : (z == 2) ? W2 : W3;
    __nv_bfloat16* dh = (z < 3) ? (g_wh + (size_t)z * DIM * DIM) : g_woh;
    __nv_bfloat16* dl = (z < 3) ? (g_wl + (size_t)z * DIM * DIM) : g_wol;

    const int bx = blockIdx.x * 32;   // n base
    const int by = blockIdx.y * 32;   // k base
    const int x = threadIdx.x, y0 = threadIdx.y;  // block (32,8)
#pragma unroll
    for (int i = 0; i < 32; i += 8)
        t[y0 + i][x] = src[(by + y0 + i) * DIM + bx + x];
    __syncthreads();
#pragma unroll
    for (int i = 0; i < 32; i += 8) {
        float v = t[x][y0 + i];
        __nv_bfloat16 h, l; split2(v, h, l);
        int o = (bx + y0 + i) * DIM + by + x;
        dh[o] = h; dl[o] = l;
    }
}

// ---------------------------------------------------------------------------
// bf16x3 split GEMM, cp.async 2-stage pipeline, BK=32, 2 CTAs/SM.
// MODE 0: QKV -> bf16 hi/lo Q/K ([b,h,n,d]) and V^T ([b,h,d,n])
// MODE 1: out proj + bias -> d_out (fp32)
// ---------------------------------------------------------------------------
#define GBK    32
#define GSTR   40                      // 80 B row stride: ldsm conflict-free, 16B-mult
#define GARR   (128 * GSTR)            // elems per array (5120)
#define GSTAGE (4 * GARR)              // elems per stage (20480)
#define GSM_BYTES (2 * GSTAGE * 2)     // 81920

template <int MODE>
__global__ __launch_bounds__(256, 2) void gemm_mma(
    const __nv_bfloat16* __restrict__ Ah, const __nv_bfloat16* __restrict__ Al,
    const __nv_bfloat16* __restrict__ Bh, const __nv_bfloat16* __restrict__ Bl,
    float* __restrict__ outp, const float* __restrict__ bo) {
    extern __shared__ __nv_bfloat16 sm[];

    const int tid  = threadIdx.x;
    const int lane = tid & 31;
    const int wid  = tid >> 5;
    const int wm   = wid & 1;
    const int wn   = wid >> 1;
    const int row0 = blockIdx.y * 128;
    const int col0 = blockIdx.x * 128;

    const __nv_bfloat16* pAh = Ah + (size_t)row0 * DIM;
    const __nv_bfloat16* pAl = Al + (size_t)row0 * DIM;
    const __nv_bfloat16* pBh = Bh + (size_t)col0 * DIM;
    const __nv_bfloat16* pBl = Bl + (size_t)col0 * DIM;

    const uint32_t sbase = smem_u32(sm);

    float acc[4][4][4];
#pragma unroll
    for (int i = 0; i < 4; i++)
#pragma unroll
        for (int j = 0; j < 4; j++)
#pragma unroll
            for (int q = 0; q < 4; q++) acc[i][j][q] = 0.0f;

    const int a_row = (lane & 15);
    const int a_kof = (lane >> 4) << 3;
    const int b_rof = ((lane >> 4) << 3) + (lane & 7);
    const int b_kof = ((lane >> 3) & 1) << 3;

    auto issue = [&](int c, int st) {
        const int k0 = c * GBK;
        const uint32_t sst = sbase + (uint32_t)(st * GSTAGE) * 2;
#pragma unroll
        for (int it = 0; it < 4; ++it) {
            const int lin = it * 256 + tid;      // 0..1023
            const int r  = lin >> 2;             // 0..127... wait 1024/4? lin>>2 up to 255
            // 128 rows x 4 cp-groups of 8 cols: lin = r*4 + cpart
            const int rr = lin >> 2;
            const int cg = (lin & 3) * 8;
            if (rr < 128) {
                const uint32_t so = (uint32_t)(rr * GSTR + cg) * 2;
                const size_t go = (size_t)rr * DIM + k0 + cg;
                cp16(sst + so,                            pAh + go);
                cp16(sst + (uint32_t)GARR * 2 + so,       pAl + go);
                cp16(sst + (uint32_t)(2 * GARR) * 2 + so, pBh + go);
                cp16(sst + (uint32_t)(3 * GARR) * 2 + so, pBl + go);
            }
            (void)r;
        }
        cp_commit();
    };

    issue(0, 0);

    const int NC = DIM / GBK;   // 32
    for (int c = 0; c < NC; ++c) {
        const int st = c & 1;
        cp_wait0();
        __syncthreads();
        if (c + 1 < NC) issue(c + 1, st ^ 1);

        const uint32_t sA = sbase + (uint32_t)(st * GSTAGE) * 2;
        const uint32_t sAh = sA;
        const uint32_t sAl = sA + (uint32_t)GARR * 2;
        const uint32_t sBh = sA + (uint32_t)(2 * GARR) * 2;
        const uint32_t sBl = sA + (uint32_t)(3 * GARR) * 2;

#pragma unroll
        for (int ks = 0; ks < GBK / 16; ++ks) {
            uint32_t bh[2][4], bl[2][4];
#pragma unroll
            for (int p = 0; p < 2; ++p) {
                const uint32_t off =
                    (uint32_t)(((wn * 32 + p * 16 + b_rof) * GSTR + ks * 16 + b_kof) * 2);
                ldsm4(bh[p][0], bh[p][1], bh[p][2], bh[p][3], sBh + off);
                ldsm4(bl[p][0], bl[p][1], bl[p][2], bl[p][3], sBl + off);
            }
#pragma unroll
            for (int mi = 0; mi < 4; ++mi) {
                uint32_t ah[4], al[4];
                const uint32_t off =
                    (uint32_t)(((wm * 64 + mi * 16 + a_row) * GSTR + ks * 16 + a_kof) * 2);
                ldsm4(ah[0], ah[1], ah[2], ah[3], sAh + off);
                ldsm4(al[0], al[1], al[2], al[3], sAl + off);
#pragma unroll
                for (int p = 0; p < 2; ++p)
#pragma unroll
                    for (int q = 0; q < 2; ++q) {
                        float* d = acc[mi][p * 2 + q];
                        mma16816(d, ah, &bh[p][q * 2]);
                        mma16816(d, ah, &bl[p][q * 2]);
                        mma16816(d, al, &bh[p][q * 2]);
                    }
            }
        }
    }

#pragma unroll
    for (int mi = 0; mi < 4; ++mi) {
#pragma unroll
        for (int nj = 0; nj < 4; ++nj) {
            const int r = row0 + wm * 64 + mi * 16 + (lane >> 2);
            const int cgl = col0 + wn * 32 + nj * 8 + (lane & 3) * 2;
#pragma unroll
            for (int half = 0; half < 2; ++half) {
                const int rr = r + half * 8;
                const float v0 = acc[mi][nj][half * 2 + 0];
                const float v1 = acc[mi][nj][half * 2 + 1];
                if (MODE == 0) {
                    const int b_ = rr >> 11, n = rr & 2047;
                    const int wsel = cgl >> 10;
                    const int c1 = cgl & 1023;
                    const int h = c1 >> 6, d0 = c1 & 63;
                    __nv_bfloat16 h0, l0, h1, l1;
                    split2(v0, h0, l0); split2(v1, h1, l1);
                    if (wsel < 2) {
                        __nv_bfloat16* dh = wsel ? g_Kh : g_Qh;
                        __nv_bfloat16* dl = wsel ? g_Kl : g_Ql;
                        const size_t o = ((size_t)(b_ * HEADS + h) * SEQ + n) * HD + d0;
                        *(__nv_bfloat162*)(dh + o) = {h0, h1};
                        *(__nv_bfloat162*)(dl + o) = {l0, l1};
                    } else {
                        const size_t o = ((size_t)(b_ * HEADS + h) * HD + d0) * SEQ + n;
                        g_Vh[o] = h0; g_Vh[o + SEQ] = h1;
                        g_Vl[o] = l0; g_Vl[o + SEQ] = l1;
                    }
                } else {
                    *(float2*)(outp + (size_t)rr * DIM + cgl) =
                        make_float2(v0 + bo[cgl], v1 + bo[cgl + 1]);
                }
            }
        }
    }
}

// ---------------------------------------------------------------------------
// Flash attention on mma.sync, bf16x3 split, cp.async 2-stage KV pipeline,
// P kept entirely in registers (C-frag -> A-frag reuse). 2 CTAs/SM.
// One block per (b*h, 128 q rows). 8 warps, each owns 16 rows x all 64 cols.
// ---------------------------------------------------------------------------
#define ASTR   72
#define AQ_ELE (128 * ASTR)            // 9216 per Q array
#define AKV_AR (64 * ASTR)             // 4608 per KV array
#define AKV_ST (4 * AKV_AR)            // 18432 per stage
#define A_KV0  (2 * AQ_ELE)            // 18432
#define A_TOTAL ((A_KV0 + 2 * AKV_ST) * 2)   // 110592 bytes

__global__ __launch_bounds__(256, 2) void attn_mma() {
    extern __shared__ __nv_bfloat16 sma[];

    const int bh   = blockIdx.y;
    const int rblk = blockIdx.x;
    const int tid  = threadIdx.x;
    const int lane = tid & 31;
    const int wid  = tid >> 5;
    const int q0   = wid * 16;

    const size_t qbase = ((size_t)bh * SEQ + rblk * 128) * HD;
    const size_t kbase = (size_t)bh * SEQ * HD;
    const size_t vbase = (size_t)bh * HD * SEQ;

    const uint32_t sbase = smem_u32(sma);
    const uint32_t uQh = sbase;
    const uint32_t uQl = sbase + (uint32_t)AQ_ELE * 2;

    // Q tile 128x64 hi/lo via cp.async
#pragma unroll
    for (int it = 0; it < 4; ++it) {
        const int lin = it * 256 + tid;
        const int r = lin >> 3, d = (lin & 7) * 8;
        const uint32_t so = (uint32_t)(r * ASTR + d) * 2;
        cp16(uQh + so, g_Qh + qbase + (size_t)r * HD + d);
        cp16(uQl + so, g_Ql + qbase + (size_t)r * HD + d);
    }
    cp_commit();

    auto issue_kv = [&](int chunk, int st) {
        const int c0 = chunk * 64;
        const uint32_t skv = sbase + (uint32_t)(A_KV0 + st * AKV_ST) * 2;
#pragma unroll
        for (int it = 0; it < 2; ++it) {
            const int lin = it * 256 + tid;
            const int r = lin >> 3, d = (lin & 7) * 8;
            const uint32_t so = (uint32_t)(r * ASTR + d) * 2;
            cp16(skv + so,                              g_Kh + kbase + (size_t)(c0 + r) * HD + d);
            cp16(skv + (uint32_t)AKV_AR * 2 + so,       g_Kl + kbase + (size_t)(c0 + r) * HD + d);
            cp16(skv + (uint32_t)(2 * AKV_AR) * 2 + so, g_Vh + vbase + (size_t)r * SEQ + c0 + d);
            cp16(skv + (uint32_t)(3 * AKV_AR) * 2 + so, g_Vl + vbase + (size_t)r * SEQ + c0 + d);
        }
        cp_commit();
    };

    issue_kv(0, 0);

    float acc_o[8][4];
#pragma unroll
    for (int j = 0; j < 8; j++)
#pragma unroll
        for (int q = 0; q < 4; q++) acc_o[j][q] = 0.0f;
    float mi[2] = {-1e30f, -1e30f}, li[2] = {0.0f, 0.0f};

    const int a_row = lane & 15;
    const int a_kof = (lane >> 4) << 3;
    const int b_rof = ((lane >> 4) << 3) + (lane & 7);
    const int b_kof = ((lane >> 3) & 1) << 3;

    const int NC = SEQ / 64;   // 32
    for (int c = 0; c < NC; ++c) {
        const int st = c & 1;
        cp_wait0();
        __syncthreads();   // stage c visible to all; all warps done reading stage c-1
        if (c + 1 < NC) issue_kv(c + 1, st ^ 1);

        const uint32_t skv = sbase + (uint32_t)(A_KV0 + st * AKV_ST) * 2;
        const uint32_t uKh = skv;
        const uint32_t uKl = skv + (uint32_t)AKV_AR * 2;
        const uint32_t uVh = skv + (uint32_t)(2 * AKV_AR) * 2;
        const uint32_t uVl = skv + (uint32_t)(3 * AKV_AR) * 2;

        // --- S = Q K^T ---
        float acc_s[8][4];
#pragma unroll
        for (int j = 0; j < 8; j++)
#pragma unroll
            for (int q = 0; q < 4; q++) acc_s[j][q] = 0.0f;

#pragma unroll
        for (int ks = 0; ks < 4; ++ks) {
            uint32_t ah[4], al[4];
            {
                const uint32_t off = (uint32_t)(((q0 + a_row) * ASTR + ks * 16 + a_kof) * 2);
                ldsm4(ah[0], ah[1], ah[2], ah[3], uQh + off);
                ldsm4(al[0], al[1], al[2], al[3], uQl + off);
            }
#pragma unroll
            for (int p = 0; p < 4; ++p) {
                uint32_t bh_[4], bl_[4];
                const uint32_t off = (uint32_t)(((p * 16 + b_rof) * ASTR + ks * 16 + b_kof) * 2);
                ldsm4(bh_[0], bh_[1], bh_[2], bh_[3], uKh + off);
                ldsm4(bl_[0], bl_[1], bl_[2], bl_[3], uKl + off);
#pragma unroll
                for (int q = 0; q < 2; ++q) {
                    float* d = acc_s[p * 2 + q];
                    mma16816(d, ah, &bh_[q * 2]);
                    mma16816(d, ah, &bl_[q * 2]);
                    mma16816(d, al, &bh_[q * 2]);
                }
            }
        }

        // --- online softmax (rows r, r+8 per thread), P stays in registers ---
#pragma unroll
        for (int half = 0; half < 2; ++half) {
            float rmax = -1e30f;
#pragma unroll
            for (int nj = 0; nj < 8; ++nj)
#pragma unroll
                for (int t = 0; t < 2; ++t) {
                    acc_s[nj][half * 2 + t] *= 0.125f;
                    rmax = fmaxf(rmax, acc_s[nj][half * 2 + t]);
                }
            rmax = fmaxf(rmax, __shfl_xor_sync(0xffffffffu, rmax, 1));
            rmax = fmaxf(rmax, __shfl_xor_sync(0xffffffffu, rmax, 2));
            const float mn = fmaxf(mi[half], rmax);
            float rsum = 0.0f;
#pragma unroll
            for (int nj = 0; nj < 8; ++nj)
#pragma unroll
                for (int t = 0; t < 2; ++t) {
                    const float e = __expf(acc_s[nj][half * 2 + t] - mn);
                    acc_s[nj][half * 2 + t] = e;
                    rsum += e;
                }
            rsum += __shfl_xor_sync(0xffffffffu, rsum, 1);
            rsum += __shfl_xor_sync(0xffffffffu, rsum, 2);
            const float alpha = __expf(mi[half] - mn);
            li[half] = li[half] * alpha + rsum;
            mi[half] = mn;
#pragma unroll
            for (int nj = 0; nj < 8; ++nj)
#pragma unroll
                for (int t = 0; t < 2; ++t) acc_o[nj][half * 2 + t] *= alpha;
        }

        // --- O += P V, P fragments built in registers from acc_s ---
#pragma unroll
        for (int ks = 0; ks < 4; ++ks) {
            uint32_t ph[4], pl[4];
            split_pack(acc_s[2 * ks][0],     acc_s[2 * ks][1],     ph[0], pl[0]);
            split_pack(acc_s[2 * ks][2],     acc_s[2 * ks][3],     ph[1], pl[1]);
            split_pack(acc_s[2 * ks + 1][0], acc_s[2 * ks + 1][1], ph[2], pl[2]);
            split_pack(acc_s[2 * ks + 1][2], acc_s[2 * ks + 1][3], ph[3], pl[3]);
#pragma unroll
            for (int p = 0; p < 4; ++p) {
                uint32_t bh_[4], bl_[4];
                const uint32_t off = (uint32_t)(((p * 16 + b_rof) * ASTR + ks * 16 + b_kof) * 2);
                ldsm4(bh_[0], bh_[1], bh_[2], bh_[3], uVh + off);
                ldsm4(bl_[0], bl_[1], bl_[2], bl_[3], uVl + off);
#pragma unroll
                for (int q = 0; q < 2; ++q) {
                    float* d = acc_o[p * 2 + q];
                    mma16816(d, ph, &bh_[q * 2]);
                    mma16816(d, ph, &bl_[q * 2]);
                    mma16816(d, pl, &bh_[q * 2]);
                }
            }
        }
    }

    // Epilogue
    const int b_ = bh >> 4, h = bh & 15;
#pragma unroll
    for (int half = 0; half < 2; ++half) {
        const float inv = 1.0f / li[half];
        const int row = rblk * 128 + q0 + (lane >> 2) + half * 8;
        const size_t mrow = ((size_t)b_ * SEQ + row) * DIM + h * HD;
#pragma unroll
        for (int nj = 0; nj < 8; ++nj) {
            const float o0 = acc_o[nj][half * 2 + 0] * inv;
            const float o1 = acc_o[nj][half * 2 + 1] * inv;
            __nv_bfloat16 h0, l0, h1, l1;
            split2(o0, h0, l0); split2(o1, h1, l1);
            const int cc = nj * 8 + (lane & 3) * 2;
            *(__nv_bfloat162*)(g_oh + mrow + cc) = {h0, h1};
            *(__nv_bfloat162*)(g_ol + mrow + cc) = {l0, l1};
        }
    }
}

// ---------------------------------------------------------------------------

extern "C" void kernel_launch(void* const* d_in, const int* in_sizes, int n_in,
                              void* d_out, int out_size) {
    (void)in_sizes; (void)n_in; (void)out_size;
    const float* x  = (const float*)d_in[0];
    const float* Wq = (const float*)d_in[1];
    const float* Wk = (const float*)d_in[2];
    const float* Wv = (const float*)d_in[3];
    const float* Wo = (const float*)d_in[4];
    const float* bo = (const float*)d_in[5];
    float* out = (float*)d_out;

    cudaFuncSetAttribute(gemm_mma<0>, cudaFuncAttributeMaxDynamicSharedMemorySize, GSM_BYTES);
    cudaFuncSetAttribute(gemm_mma<1>, cudaFuncAttributeMaxDynamicSharedMemorySize, GSM_BYTES);
    cudaFuncSetAttribute(attn_mma,    cudaFuncAttributeMaxDynamicSharedMemorySize, A_TOTAL);

    __nv_bfloat16 *wh, *wl, *woh, *wol, *xh, *xl, *oh, *ol;
    cudaGetSymbolAddress((void**)&wh,  g_wh);
    cudaGetSymbolAddress((void**)&wl,  g_wl);
    cudaGetSymbolAddress((void**)&woh, g_woh);
    cudaGetSymbolAddress((void**)&wol, g_wol);
    cudaGetSymbolAddress((void**)&xh,  g_xh);
    cudaGetSymbolAddress((void**)&xl,  g_xl);
    cudaGetSymbolAddress((void**)&oh,  g_oh);
    cudaGetSymbolAddress((void**)&ol,  g_ol);

    split_x_kernel<<<MROWS * DIM / 1024, 256>>>(x);
    transpose_split4<<<dim3(32, 32, 4), dim3(32, 8)>>>(Wq, Wk, Wv, Wo);

    gemm_mma<0><<<dim3(24, 64), 256, GSM_BYTES>>>(xh, xl, wh, wl, nullptr, nullptr);
    attn_mma<<<dim3(16, 64), 256, A_TOTAL>>>();
    gemm_mma<1><<<dim3(8, 64), 256, GSM_BYTES>>>(oh, ol, woh, wol, out, bo);
}